// round 7
// baseline (speedup 1.0000x reference)
#include <cuda_runtime.h>
#include <math.h>

// ---------------- problem dims ----------------
#define CDIM 512
#define INDIM 256
#define NHEAD 4
#define DHEAD 128
#define FANOUT 16
#define NCLS 47
#define N0 256
#define N1 4096
#define N2 65536

// ---------------- scratch (static device globals; no runtime alloc) ----------------
__device__ float g_s0a[N0 * CDIM];
__device__ float g_s0b[N0 * CDIM];
__device__ float g_s1a[N1 * CDIM];
__device__ float g_s1b[N1 * CDIM];
__device__ float g_s2[(long long)N2 * CDIM];
__device__ float g_concat[N1 * 2 * CDIM];
__device__ float g_hlocal[N1 * CDIM];
__device__ float g_h1[N1 * CDIM];
__device__ float g_qkv[N1 * 3 * CDIM];
__device__ float g_scores[(long long)NHEAD * N1 * N1];   // 268 MB
__device__ float g_attno[N1 * CDIM];
__device__ float g_h2[N1 * CDIM];
__device__ float g_ffnmid[N1 * 2 * CDIM];

// =====================================================================
// Double-buffered tiled fp32 GEMM.
//   Y[M,N] = op( X[M,K] * W )  with W [N,K] (TRANSB) or [K,N] (!TRANSB)
// 256 threads; thread tile = (BM/16) x (BN/16).
// Requires: K % BK == 0 (all K here are multiples of 16), ldx/ldw/offsets
// multiples of 4 floats (holds for all call sites).
// Epilogue MODE:
//   0: v + bias[col]
//   1: (v + bias[col]) * rowmask[row]                (embedding)
//   2: v * alpha                                     (scores / PV)
//   3: relu(v + bias[col])                           (FFN mid)
//   4: (res[row,col] + v + bias[col]) * rowmask[row] (final state)
// blockIdx.z batches with strides sX/sW/sY.
// =====================================================================
template <int BM, int BN, int BK, int MODE, bool TRANSB>
__global__ void __launch_bounds__(256, 2) gemm_kernel(
    const float* __restrict__ Xb, const float* __restrict__ Wb,
    const float* __restrict__ bias, const float* __restrict__ res,
    const float* __restrict__ rowmask, float* __restrict__ Yb,
    int M, int N, int K, int ldx, int ldw, int ldy,
    long long sX, long long sW, long long sY, float alpha)
{
    constexpr int TM = BM / 16;
    constexpr int TN = BN / 16;

    const float* X = Xb + (long long)blockIdx.z * sX;
    const float* W = Wb + (long long)blockIdx.z * sW;
    float*       Y = Yb + (long long)blockIdx.z * sY;

    __shared__ float As[2][BK][BM];
    __shared__ float Bs[2][BK][BN];

    const int tid = threadIdx.x;
    const int tr  = tid >> 4;     // 0..15
    const int tc  = tid & 15;     // 0..15
    const int m0  = blockIdx.x * BM;
    const int n0  = blockIdx.y * BN;

    // Global->reg load mappings: 256 threads x float4 exactly cover each tile.
    // (BM*BK/4 == 256 and BN*BK/4 == 256 for both tile configs.)
    const int arow = (tid * 4) / BK;          // A: row within tile
    const int akq  = (tid * 4) % BK;          // A: k offset (mult of 4)
    const int brow = (tid * 4) / BK;          // B TRANSB: n-row within tile
    const int bkq  = (tid * 4) % BK;
    const int bkk  = (tid * 4) / BN;          // B NN: k-row within tile
    const int bnq  = (tid * 4) % BN;          // B NN: n offset (mult of 4)

    const float* aptr  = X + (long long)(m0 + arow) * ldx + akq;
    const bool   aval  = (m0 + arow) < M;
    const float* bptrT = W + (long long)(n0 + brow) * ldw + bkq;
    const bool   bvalT = (n0 + brow) < N;
    const float* bptrN = W + (long long)bkk * ldw + n0 + bnq;
    const bool   bvalN = (n0 + bnq) < N;      // N mult of 4 at all NN sites

    const float4 z4 = make_float4(0.f, 0.f, 0.f, 0.f);

    float acc[TM][TN];
#pragma unroll
    for (int i = 0; i < TM; i++)
#pragma unroll
        for (int j = 0; j < TN; j++) acc[i][j] = 0.f;

    float4 ra, rb;

    // ---- prologue: tile 0 -> buffer 0 ----
    ra = aval ? *reinterpret_cast<const float4*>(aptr) : z4;
    if (TRANSB) rb = bvalT ? *reinterpret_cast<const float4*>(bptrT) : z4;
    else        rb = bvalN ? *reinterpret_cast<const float4*>(bptrN) : z4;

    As[0][akq + 0][arow] = ra.x; As[0][akq + 1][arow] = ra.y;
    As[0][akq + 2][arow] = ra.z; As[0][akq + 3][arow] = ra.w;
    if (TRANSB) {
        Bs[0][bkq + 0][brow] = rb.x; Bs[0][bkq + 1][brow] = rb.y;
        Bs[0][bkq + 2][brow] = rb.z; Bs[0][bkq + 3][brow] = rb.w;
    } else {
        *reinterpret_cast<float4*>(&Bs[0][bkk][bnq]) = rb;
    }
    __syncthreads();

    const int nk = K / BK;
    for (int t = 0; t < nk; t++) {
        const int buf = t & 1;
        const bool more = (t + 1) < nk;
        if (more) {
            const int k0 = (t + 1) * BK;
            ra = aval ? *reinterpret_cast<const float4*>(aptr + k0) : z4;
            if (TRANSB) rb = bvalT ? *reinterpret_cast<const float4*>(bptrT + k0) : z4;
            else        rb = bvalN ? *reinterpret_cast<const float4*>(bptrN + (long long)k0 * ldw) : z4;
        }

#pragma unroll
        for (int k = 0; k < BK; k++) {
            float a[TM], b[TN];
#pragma unroll
            for (int i = 0; i < TM / 4; i++) {
                float4 v = *reinterpret_cast<const float4*>(&As[buf][k][tr * TM + i * 4]);
                a[i * 4 + 0] = v.x; a[i * 4 + 1] = v.y;
                a[i * 4 + 2] = v.z; a[i * 4 + 3] = v.w;
            }
#pragma unroll
            for (int j = 0; j < TN / 4; j++) {
                float4 v = *reinterpret_cast<const float4*>(&Bs[buf][k][tc * TN + j * 4]);
                b[j * 4 + 0] = v.x; b[j * 4 + 1] = v.y;
                b[j * 4 + 2] = v.z; b[j * 4 + 3] = v.w;
            }
#pragma unroll
            for (int i = 0; i < TM; i++)
#pragma unroll
                for (int j = 0; j < TN; j++) acc[i][j] += a[i] * b[j];
        }

        if (more) {
            const int nb = buf ^ 1;
            As[nb][akq + 0][arow] = ra.x; As[nb][akq + 1][arow] = ra.y;
            As[nb][akq + 2][arow] = ra.z; As[nb][akq + 3][arow] = ra.w;
            if (TRANSB) {
                Bs[nb][bkq + 0][brow] = rb.x; Bs[nb][bkq + 1][brow] = rb.y;
                Bs[nb][bkq + 2][brow] = rb.z; Bs[nb][bkq + 3][brow] = rb.w;
            } else {
                *reinterpret_cast<float4*>(&Bs[nb][bkk][bnq]) = rb;
            }
            __syncthreads();
        }
    }

    // ---- epilogue ----
#pragma unroll
    for (int i = 0; i < TM; i++) {
        const int gr = m0 + tr * TM + i;
        if (gr >= M) continue;
#pragma unroll
        for (int j = 0; j < TN; j++) {
            const int gc = n0 + tc * TN + j;
            if (gc >= N) continue;
            float v = acc[i][j];
            if (MODE == 0)      v = v + bias[gc];
            else if (MODE == 1) v = (v + bias[gc]) * rowmask[gr];
            else if (MODE == 2) v = v * alpha;
            else if (MODE == 3) v = fmaxf(v + bias[gc], 0.f);
            else if (MODE == 4) v = (res[(long long)gr * ldy + gc] + v + bias[gc]) * rowmask[gr];
            Y[(long long)gr * ldy + gc] = v;
        }
    }
}

// =====================================================================
// Masked-mean neighbor aggregation + concat (HBM-bound, ~25us total)
// =====================================================================
__global__ void __launch_bounds__(128) agg_concat_kernel(
    float* __restrict__ out, const float* __restrict__ sf,
    const float* __restrict__ child, const int* __restrict__ nbm)
{
    const int i = blockIdx.x;
    const int tid = threadIdx.x;
    __shared__ float mk[FANOUT];
    __shared__ float invd;
    if (tid < FANOUT) mk[tid] = (float)nbm[i * FANOUT + tid];
    __syncthreads();
    if (tid == 0) {
        float s = 0.f;
#pragma unroll
        for (int f = 0; f < FANOUT; f++) s += mk[f];
        invd = 1.f / fmaxf(s, 1.f);
    }
    __syncthreads();
    const float dinv = invd;
    const long long ob = (long long)i * (2 * CDIM);
    *reinterpret_cast<float4*>(out + ob + tid * 4) =
        *reinterpret_cast<const float4*>(sf + (long long)i * CDIM + tid * 4);
    float4 acc = make_float4(0.f, 0.f, 0.f, 0.f);
    const float* cb = child + (long long)i * FANOUT * CDIM + tid * 4;
#pragma unroll
    for (int f = 0; f < FANOUT; f++) {
        float4 v = *reinterpret_cast<const float4*>(cb + f * CDIM);
        float w = mk[f];
        acc.x += v.x * w; acc.y += v.y * w; acc.z += v.z * w; acc.w += v.w * w;
    }
    acc.x *= dinv; acc.y *= dinv; acc.z *= dinv; acc.w *= dinv;
    *reinterpret_cast<float4*>(out + ob + CDIM + tid * 4) = acc;
}

// =====================================================================
// Residual + LayerNorm over C=512
// =====================================================================
__global__ void __launch_bounds__(128) ln_res_kernel(
    float* __restrict__ out, const float* __restrict__ a, const float* __restrict__ b,
    const float* __restrict__ g, const float* __restrict__ be)
{
    const long long base = (long long)blockIdx.x * CDIM;
    const int tid = threadIdx.x;
    float4 va = *reinterpret_cast<const float4*>(a + base + tid * 4);
    float4 vb = *reinterpret_cast<const float4*>(b + base + tid * 4);
    float x0 = va.x + vb.x, x1 = va.y + vb.y, x2 = va.z + vb.z, x3 = va.w + vb.w;
    float s = x0 + x1 + x2 + x3;
    float q = x0 * x0 + x1 * x1 + x2 * x2 + x3 * x3;
#pragma unroll
    for (int o = 16; o; o >>= 1) {
        s += __shfl_xor_sync(0xffffffffu, s, o);
        q += __shfl_xor_sync(0xffffffffu, q, o);
    }
    __shared__ float shs[4], shq[4];
    if ((tid & 31) == 0) { shs[tid >> 5] = s; shq[tid >> 5] = q; }
    __syncthreads();
    s = shs[0] + shs[1] + shs[2] + shs[3];
    q = shq[0] + shq[1] + shq[2] + shq[3];
    const float mu  = s * (1.f / CDIM);
    const float var = q * (1.f / CDIM) - mu * mu;
    const float r   = rsqrtf(var + 1e-5f);
    float4 vg  = *reinterpret_cast<const float4*>(g + tid * 4);
    float4 vbe = *reinterpret_cast<const float4*>(be + tid * 4);
    float4 o4;
    o4.x = (x0 - mu) * r * vg.x + vbe.x;
    o4.y = (x1 - mu) * r * vg.y + vbe.y;
    o4.z = (x2 - mu) * r * vg.z + vbe.z;
    o4.w = (x3 - mu) * r * vg.w + vbe.w;
    *reinterpret_cast<float4*>(out + base + tid * 4) = o4;
}

// =====================================================================
// Row softmax over length n (n = CNT*256). grid = (n_rows, n_heads).
// =====================================================================
template <int CNT>
__global__ void __launch_bounds__(256) softmax_kernel(float* __restrict__ S, int n)
{
    float* row = S + ((long long)blockIdx.y * n + blockIdx.x) * n;
    const int tid = threadIdx.x;
    float vals[CNT];
#pragma unroll
    for (int t = 0; t < CNT; t++) vals[t] = row[tid + t * 256];
    float m = -1e30f;
#pragma unroll
    for (int t = 0; t < CNT; t++) m = fmaxf(m, vals[t]);
    __shared__ float sh[8];
#pragma unroll
    for (int o = 16; o; o >>= 1) m = fmaxf(m, __shfl_xor_sync(0xffffffffu, m, o));
    if ((tid & 31) == 0) sh[tid >> 5] = m;
    __syncthreads();
    float mm = sh[0];
#pragma unroll
    for (int w = 1; w < 8; w++) mm = fmaxf(mm, sh[w]);
    float s = 0.f;
#pragma unroll
    for (int t = 0; t < CNT; t++) { vals[t] = expf(vals[t] - mm); s += vals[t]; }
    __syncthreads();
#pragma unroll
    for (int o = 16; o; o >>= 1) s += __shfl_xor_sync(0xffffffffu, s, o);
    if ((tid & 31) == 0) sh[tid >> 5] = s;
    __syncthreads();
    float tot = 0.f;
#pragma unroll
    for (int w = 0; w < 8; w++) tot += sh[w];
    const float inv = 1.f / tot;
#pragma unroll
    for (int t = 0; t < CNT; t++) row[tid + t * 256] = vals[t] * inv;
}

// =====================================================================
// Host-side launch helper: picks 128x128x8 (big) or 64x64x16 (small).
// =====================================================================
template <int MODE, bool TB>
static inline void launch_gemm(bool small, const float* X, const float* W,
                               const float* bias, const float* res, const float* rm,
                               float* Y, int M, int N, int K,
                               int ldx, int ldw, int ldy,
                               long long sX = 0, long long sW = 0, long long sY = 0,
                               int batch = 1, float alpha = 1.f)
{
    if (small) {
        dim3 grid((M + 63) / 64, (N + 63) / 64, batch);
        gemm_kernel<64, 64, 16, MODE, TB><<<grid, 256>>>(
            X, W, bias, res, rm, Y, M, N, K, ldx, ldw, ldy, sX, sW, sY, alpha);
    } else {
        dim3 grid((M + 127) / 128, (N + 127) / 128, batch);
        gemm_kernel<128, 128, 8, MODE, TB><<<grid, 256>>>(
            X, W, bias, res, rm, Y, M, N, K, ldx, ldw, ldy, sX, sW, sY, alpha);
    }
}

// Cached scratch pointers (symbol addresses are stable; capture-safe).
static float *s0a, *s0b, *s1a, *s1b, *s2, *cc, *hl, *h1, *qkvp, *scp, *ao, *h2p, *fm;
static bool g_ptrs_ready = false;

static void resolve_ptrs()
{
    if (g_ptrs_ready) return;
    cudaGetSymbolAddress((void**)&s0a, g_s0a);
    cudaGetSymbolAddress((void**)&s0b, g_s0b);
    cudaGetSymbolAddress((void**)&s1a, g_s1a);
    cudaGetSymbolAddress((void**)&s1b, g_s1b);
    cudaGetSymbolAddress((void**)&s2,  g_s2);
    cudaGetSymbolAddress((void**)&cc,  g_concat);
    cudaGetSymbolAddress((void**)&hl,  g_hlocal);
    cudaGetSymbolAddress((void**)&h1,  g_h1);
    cudaGetSymbolAddress((void**)&qkvp, g_qkv);
    cudaGetSymbolAddress((void**)&scp,  g_scores);
    cudaGetSymbolAddress((void**)&ao,  g_attno);
    cudaGetSymbolAddress((void**)&h2p, g_h2);
    cudaGetSymbolAddress((void**)&fm,  g_ffnmid);
    g_ptrs_ready = true;
}

extern "C" void kernel_launch(void* const* d_in, const int* in_sizes, int n_in,
                              void* d_out, int out_size)
{
    (void)in_sizes; (void)n_in; (void)out_size;
    const float* feats0  = (const float*)d_in[0];
    const float* feats1  = (const float*)d_in[1];
    const float* feats2  = (const float*)d_in[2];
    const float* nmask0  = (const float*)d_in[3];
    const float* nmask1  = (const float*)d_in[4];
    const float* nmask2  = (const float*)d_in[5];
    const int*   nbmask0 = (const int*)d_in[6];
    const int*   nbmask1 = (const int*)d_in[7];
    const float* emb_w   = (const float*)d_in[8];
    const float* emb_b   = (const float*)d_in[9];
    const float* sage_w  = (const float*)d_in[10];
    const float* sage_b  = (const float*)d_in[11];
    const float* qkv_w   = (const float*)d_in[12];
    const float* qkv_b   = (const float*)d_in[13];
    const float* out_w   = (const float*)d_in[14];
    const float* out_b   = (const float*)d_in[15];
    const float* n1_g    = (const float*)d_in[16];
    const float* n1_b    = (const float*)d_in[17];
    const float* n2_g    = (const float*)d_in[18];
    const float* n2_b    = (const float*)d_in[19];
    const float* ffn_w1  = (const float*)d_in[20];
    const float* ffn_b1  = (const float*)d_in[21];
    const float* ffn_w2  = (const float*)d_in[22];
    const float* ffn_b2  = (const float*)d_in[23];
    const float* cls_w   = (const float*)d_in[24];
    const float* cls_b   = (const float*)d_in[25];
    float* out = (float*)d_out;

    resolve_ptrs();

    // ---- embeddings: state_d = (feats_d @ emb_w^T + emb_b) * nmask_d ----
    launch_gemm<1, true>(false, feats2, emb_w, emb_b, nullptr, nmask2, s2,
                         N2, CDIM, INDIM, INDIM, INDIM, CDIM);
    launch_gemm<1, true>(false, feats1, emb_w, emb_b, nullptr, nmask1, s1a,
                         N1, CDIM, INDIM, INDIM, INDIM, CDIM);
    launch_gemm<1, true>(true, feats0, emb_w, emb_b, nullptr, nmask0, s0a,
                         N0, CDIM, INDIM, INDIM, INDIM, CDIM);

    // (li, n, sf, child, out, nbm, nmask) — ping-pong reproduces prev-snapshot
    struct Step { int li, n; float *sf, *child, *outb; const int* nbm; const float* nm; };
    Step steps[3] = {
        {0, N1, s1a, s2,  s1b, nbmask1, nmask1},
        {0, N0, s0a, s1a, s0b, nbmask0, nmask0},
        {1, N0, s0b, s1b, s0a, nbmask0, nmask0},
    };

    const float scale = 1.f / sqrtf((float)DHEAD);

    for (int si = 0; si < 3; si++) {
        const Step& st = steps[si];
        const int li = st.li, n = st.n;
        const bool sm = (n == N0);
        const float* sw  = sage_w + (long long)li * CDIM * 2 * CDIM;
        const float* sb  = sage_b + li * CDIM;
        const float* qw  = qkv_w  + (long long)li * 3 * CDIM * CDIM;
        const float* qb  = qkv_b  + li * 3 * CDIM;
        const float* ow  = out_w  + (long long)li * CDIM * CDIM;
        const float* ob  = out_b  + li * CDIM;
        const float* g1  = n1_g + li * CDIM, *b1 = n1_b + li * CDIM;
        const float* g2  = n2_g + li * CDIM, *b2 = n2_b + li * CDIM;
        const float* fw1 = ffn_w1 + (long long)li * 2 * CDIM * CDIM;
        const float* fb1 = ffn_b1 + li * 2 * CDIM;
        const float* fw2 = ffn_w2 + (long long)li * CDIM * 2 * CDIM;
        const float* fb2 = ffn_b2 + li * CDIM;

        // 1) masked-mean aggregate + concat  -> cc [n, 1024]
        agg_concat_kernel<<<n, 128>>>(cc, st.sf, st.child, st.nbm);
        // 2) h_local = cc @ sage_w^T + sage_b
        launch_gemm<0, true>(sm, cc, sw, sb, nullptr, nullptr, hl,
                             n, CDIM, 2 * CDIM, 2 * CDIM, 2 * CDIM, CDIM);
        // 3) h1 = LN(sf + h_local)
        ln_res_kernel<<<n, 128>>>(h1, st.sf, hl, g1, b1);
        // 4) qkv = h1 @ qkv_w^T + qkv_b
        launch_gemm<0, true>(sm, h1, qw, qb, nullptr, nullptr, qkvp,
                             n, 3 * CDIM, CDIM, CDIM, CDIM, 3 * CDIM);
        // 5) scores[h] = scale * Q_h @ K_h^T   (batched over 4 heads)
        launch_gemm<2, true>(sm, qkvp, qkvp + CDIM, nullptr, nullptr, nullptr, scp,
                             n, n, DHEAD, 3 * CDIM, 3 * CDIM, n,
                             DHEAD, DHEAD, (long long)n * n, NHEAD, scale);
        // 6) softmax over keys
        if (n == N1) softmax_kernel<16><<<dim3(N1, NHEAD), 256>>>(scp, n);
        else         softmax_kernel<1><<<dim3(N0, NHEAD), 256>>>(scp, n);
        // 7) O_h = A_h @ V_h  (nn GEMM, batched over heads; head-interleaved out)
        launch_gemm<2, false>(sm, scp, qkvp + 2 * CDIM, nullptr, nullptr, nullptr, ao,
                              n, DHEAD, n, n, 3 * CDIM, CDIM,
                              (long long)n * n, DHEAD, DHEAD, NHEAD, 1.f);
        // 8) proj = O @ out_w^T + out_b
        launch_gemm<0, true>(sm, ao, ow, ob, nullptr, nullptr, hl,
                             n, CDIM, CDIM, CDIM, CDIM, CDIM);
        // 9) h2 = LN(h1 + proj)
        ln_res_kernel<<<n, 128>>>(h2p, h1, hl, g2, b2);
        // 10) mid = relu(h2 @ ffn_w1^T + ffn_b1)
        launch_gemm<3, true>(sm, h2p, fw1, fb1, nullptr, nullptr, fm,
                             n, 2 * CDIM, CDIM, CDIM, CDIM, 2 * CDIM);
        // 11) state = (h2 + mid @ ffn_w2^T + ffn_b2) * nmask
        launch_gemm<4, true>(sm, fm, fw2, fb2, h2p, st.nm, st.outb,
                             n, CDIM, 2 * CDIM, 2 * CDIM, 2 * CDIM, CDIM);
    }

    // ---- classifier: out = state0 @ cls_w^T + cls_b ----
    launch_gemm<0, true>(true, s0a, cls_w, cls_b, nullptr, nullptr, out,
                         N0, NCLS, CDIM, CDIM, CDIM, NCLS);
}

// round 8
// speedup vs baseline: 1.5782x; 1.5782x over previous
#include <cuda_runtime.h>
#include <cuda_bf16.h>
#include <math.h>

// ---------------- problem dims ----------------
#define CDIM 512
#define INDIM 256
#define NHEAD 4
#define DHEAD 128
#define FANOUT 16
#define NCLS 47
#define N0 256
#define N1 4096
#define N2 65536

// ---------------- scratch (static device globals; no runtime alloc) ----------------
__device__ float g_s0a[N0 * CDIM];
__device__ float g_s0b[N0 * CDIM];
__device__ float g_s1a[N1 * CDIM];
__device__ float g_s1b[N1 * CDIM];
__device__ float g_s2[(long long)N2 * CDIM];
__device__ float g_concat[N1 * 2 * CDIM];
__device__ float g_hlocal[N1 * CDIM];
__device__ float g_h1[N1 * CDIM];
__device__ float g_qkv[N1 * 3 * CDIM];
__device__ float g_scores[(long long)NHEAD * N1 * N1];   // 268 MB
__device__ float g_attno[N1 * CDIM];
__device__ float g_h2[N1 * CDIM];
__device__ float g_ffnmid[N1 * 2 * CDIM];

// =====================================================================
// Tensor-core GEMM via mma.sync bf16 with split-bf16 (3-pass) accuracy.
//   Y[M,N] = op( X[M,K] * W )  with W [N,K] (TRANSB) or [K,N] (!TRANSB)
// Block tile 128x64x32, 256 threads = 8 warps (4 x 2), warp tile 32x32.
// Each fp32 value x = hi + lo (both bf16); product uses hi*hi + hi*lo + lo*hi.
// Requires K % 32 == 0 and float4-aligned pointers/lds (all call sites OK).
// Epilogue MODE:
//   0: v + bias[col]
//   1: (v + bias[col]) * rowmask[row]                (embedding)
//   2: v * alpha                                     (scores / PV)
//   3: relu(v + bias[col])                           (FFN mid)
//   4: (res[row,col] + v + bias[col]) * rowmask[row] (final state)
// blockIdx.z batches with strides sX/sW/sY.
// =====================================================================

__device__ __forceinline__ void mma16816(float* c, const unsigned* a, const unsigned* b)
{
    asm volatile(
        "mma.sync.aligned.m16n8k16.row.col.f32.bf16.bf16.f32 "
        "{%0,%1,%2,%3}, {%4,%5,%6,%7}, {%8,%9}, {%0,%1,%2,%3};\n"
        : "+f"(c[0]), "+f"(c[1]), "+f"(c[2]), "+f"(c[3])
        : "r"(a[0]), "r"(a[1]), "r"(a[2]), "r"(a[3]), "r"(b[0]), "r"(b[1]));
}

template <int MODE, bool TRANSB>
__global__ void __launch_bounds__(256) mma_gemm_kernel(
    const float* __restrict__ Xb, const float* __restrict__ Wb,
    const float* __restrict__ bias, const float* __restrict__ res,
    const float* __restrict__ rowmask, float* __restrict__ Yb,
    int M, int N, int K, int ldx, int ldw, int ldy,
    long long sX, long long sW, long long sY, float alpha)
{
    constexpr int BM = 128, BN = 64, BK = 32;
    constexpr int LDA = 40, LDB = 40;   // bf16 pitch: 20 banks/row -> conflict-free frags

    const float* X = Xb + (long long)blockIdx.z * sX;
    const float* W = Wb + (long long)blockIdx.z * sW;
    float*       Y = Yb + (long long)blockIdx.z * sY;

    __shared__ __nv_bfloat16 Ahi[BM * LDA], Alo[BM * LDA];
    __shared__ __nv_bfloat16 Bhi[BN * LDB], Blo[BN * LDB];

    const int tid  = threadIdx.x;
    const int warp = tid >> 5;
    const int lane = tid & 31;
    const int wm   = warp & 3;          // m-offset 32*wm
    const int wn   = warp >> 2;         // n-offset 32*wn
    const int m0   = blockIdx.x * BM;
    const int n0   = blockIdx.y * BN;

    const int r  = lane >> 2;           // fragment row/col group
    const int c2 = (lane & 3) * 2;      // fragment k-pair / col-pair

    float acc[2][4][4];
#pragma unroll
    for (int mt = 0; mt < 2; mt++)
#pragma unroll
        for (int nt = 0; nt < 4; nt++)
#pragma unroll
            for (int e = 0; e < 4; e++) acc[mt][nt][e] = 0.f;

    const float4 z4 = make_float4(0.f, 0.f, 0.f, 0.f);

    for (int k0 = 0; k0 < K; k0 += BK) {
        // ---- load + convert A tile [BM x BK] (always row-major in K) ----
#pragma unroll
        for (int it = 0; it < 4; it++) {
            int idx = tid + it * 256;           // 1024 float4 slots
            int row = idx >> 3;                 // 8 float4 per row
            int kq  = (idx & 7) << 2;
            float4 v = ((m0 + row) < M)
                ? *reinterpret_cast<const float4*>(X + (long long)(m0 + row) * ldx + k0 + kq)
                : z4;
            float f[4] = {v.x, v.y, v.z, v.w};
            __nv_bfloat16* ph = &Ahi[row * LDA + kq];
            __nv_bfloat16* pl = &Alo[row * LDA + kq];
#pragma unroll
            for (int e = 0; e < 4; e++) {
                __nv_bfloat16 h = __float2bfloat16(f[e]);
                ph[e] = h;
                pl[e] = __float2bfloat16(f[e] - __bfloat162float(h));
            }
        }
        // ---- load + convert B tile into [n][k] layout ----
        if (TRANSB) {
            // W[N,K]: rows are n, contiguous in k — direct
#pragma unroll
            for (int it = 0; it < 2; it++) {
                int idx = tid + it * 256;       // 512 float4 slots
                int row = idx >> 3;             // n within tile
                int kq  = (idx & 7) << 2;
                float4 v = ((n0 + row) < N)
                    ? *reinterpret_cast<const float4*>(W + (long long)(n0 + row) * ldw + k0 + kq)
                    : z4;
                float f[4] = {v.x, v.y, v.z, v.w};
                __nv_bfloat16* ph = &Bhi[row * LDB + kq];
                __nv_bfloat16* pl = &Blo[row * LDB + kq];
#pragma unroll
                for (int e = 0; e < 4; e++) {
                    __nv_bfloat16 h = __float2bfloat16(f[e]);
                    ph[e] = h;
                    pl[e] = __float2bfloat16(f[e] - __bfloat162float(h));
                }
            }
        } else {
            // W[K,N]: rows are k, contiguous in n — transpose during store
#pragma unroll
            for (int it = 0; it < 2; it++) {
                int idx = tid + it * 256;       // 512 float4 slots
                int kk  = idx >> 4;             // k within tile (16 float4 per k-row)
                int nq  = (idx & 15) << 2;
                float4 v = ((n0 + nq + 3) < N)
                    ? *reinterpret_cast<const float4*>(W + (long long)(k0 + kk) * ldw + n0 + nq)
                    : z4;
                float f[4] = {v.x, v.y, v.z, v.w};
#pragma unroll
                for (int e = 0; e < 4; e++) {
                    float x = ((n0 + nq + e) < N) ? f[e] : 0.f;
                    __nv_bfloat16 h = __float2bfloat16(x);
                    Bhi[(nq + e) * LDB + kk] = h;
                    Blo[(nq + e) * LDB + kk] = __float2bfloat16(x - __bfloat162float(h));
                }
            }
        }
        __syncthreads();

        // ---- compute: 2 k-steps of 16 ----
#pragma unroll
        for (int ks = 0; ks < 2; ks++) {
            const int koff = ks * 16;
            unsigned ah[2][4], al[2][4], bh[4][2], bl[4][2];
#pragma unroll
            for (int mt = 0; mt < 2; mt++) {
                const int rb = (wm * 32 + mt * 16 + r) * LDA + koff + c2;
                ah[mt][0] = *reinterpret_cast<const unsigned*>(&Ahi[rb]);
                ah[mt][1] = *reinterpret_cast<const unsigned*>(&Ahi[rb + 8 * LDA]);
                ah[mt][2] = *reinterpret_cast<const unsigned*>(&Ahi[rb + 8]);
                ah[mt][3] = *reinterpret_cast<const unsigned*>(&Ahi[rb + 8 * LDA + 8]);
                al[mt][0] = *reinterpret_cast<const unsigned*>(&Alo[rb]);
                al[mt][1] = *reinterpret_cast<const unsigned*>(&Alo[rb + 8 * LDA]);
                al[mt][2] = *reinterpret_cast<const unsigned*>(&Alo[rb + 8]);
                al[mt][3] = *reinterpret_cast<const unsigned*>(&Alo[rb + 8 * LDA + 8]);
            }
#pragma unroll
            for (int nt = 0; nt < 4; nt++) {
                const int cb = (wn * 32 + nt * 8 + r) * LDB + koff + c2;
                bh[nt][0] = *reinterpret_cast<const unsigned*>(&Bhi[cb]);
                bh[nt][1] = *reinterpret_cast<const unsigned*>(&Bhi[cb + 8]);
                bl[nt][0] = *reinterpret_cast<const unsigned*>(&Blo[cb]);
                bl[nt][1] = *reinterpret_cast<const unsigned*>(&Blo[cb + 8]);
            }
#pragma unroll
            for (int mt = 0; mt < 2; mt++)
#pragma unroll
                for (int nt = 0; nt < 4; nt++) {
                    mma16816(acc[mt][nt], ah[mt], bh[nt]);
                    mma16816(acc[mt][nt], ah[mt], bl[nt]);
                    mma16816(acc[mt][nt], al[mt], bh[nt]);
                }
        }
        __syncthreads();
    }

    // ---- epilogue ----
#pragma unroll
    for (int mt = 0; mt < 2; mt++) {
#pragma unroll
        for (int nt = 0; nt < 4; nt++) {
#pragma unroll
            for (int e = 0; e < 4; e++) {
                const int gr = m0 + wm * 32 + mt * 16 + r + (e >= 2 ? 8 : 0);
                const int gc = n0 + wn * 32 + nt * 8 + c2 + (e & 1);
                if (gr >= M || gc >= N) continue;
                float v = acc[mt][nt][e];
                if (MODE == 0)      v = v + bias[gc];
                else if (MODE == 1) v = (v + bias[gc]) * rowmask[gr];
                else if (MODE == 2) v = v * alpha;
                else if (MODE == 3) v = fmaxf(v + bias[gc], 0.f);
                else if (MODE == 4) v = (res[(long long)gr * ldy + gc] + v + bias[gc]) * rowmask[gr];
                Y[(long long)gr * ldy + gc] = v;
            }
        }
    }
}

// =====================================================================
// Masked-mean neighbor aggregation + concat (HBM-bound, ~25us total)
// =====================================================================
__global__ void __launch_bounds__(128) agg_concat_kernel(
    float* __restrict__ out, const float* __restrict__ sf,
    const float* __restrict__ child, const int* __restrict__ nbm)
{
    const int i = blockIdx.x;
    const int tid = threadIdx.x;
    __shared__ float mk[FANOUT];
    __shared__ float invd;
    if (tid < FANOUT) mk[tid] = (float)nbm[i * FANOUT + tid];
    __syncthreads();
    if (tid == 0) {
        float s = 0.f;
#pragma unroll
        for (int f = 0; f < FANOUT; f++) s += mk[f];
        invd = 1.f / fmaxf(s, 1.f);
    }
    __syncthreads();
    const float dinv = invd;
    const long long ob = (long long)i * (2 * CDIM);
    *reinterpret_cast<float4*>(out + ob + tid * 4) =
        *reinterpret_cast<const float4*>(sf + (long long)i * CDIM + tid * 4);
    float4 acc = make_float4(0.f, 0.f, 0.f, 0.f);
    const float* cb = child + (long long)i * FANOUT * CDIM + tid * 4;
#pragma unroll
    for (int f = 0; f < FANOUT; f++) {
        float4 v = *reinterpret_cast<const float4*>(cb + f * CDIM);
        float w = mk[f];
        acc.x += v.x * w; acc.y += v.y * w; acc.z += v.z * w; acc.w += v.w * w;
    }
    acc.x *= dinv; acc.y *= dinv; acc.z *= dinv; acc.w *= dinv;
    *reinterpret_cast<float4*>(out + ob + CDIM + tid * 4) = acc;
}

// =====================================================================
// Residual + LayerNorm over C=512
// =====================================================================
__global__ void __launch_bounds__(128) ln_res_kernel(
    float* __restrict__ out, const float* __restrict__ a, const float* __restrict__ b,
    const float* __restrict__ g, const float* __restrict__ be)
{
    const long long base = (long long)blockIdx.x * CDIM;
    const int tid = threadIdx.x;
    float4 va = *reinterpret_cast<const float4*>(a + base + tid * 4);
    float4 vb = *reinterpret_cast<const float4*>(b + base + tid * 4);
    float x0 = va.x + vb.x, x1 = va.y + vb.y, x2 = va.z + vb.z, x3 = va.w + vb.w;
    float s = x0 + x1 + x2 + x3;
    float q = x0 * x0 + x1 * x1 + x2 * x2 + x3 * x3;
#pragma unroll
    for (int o = 16; o; o >>= 1) {
        s += __shfl_xor_sync(0xffffffffu, s, o);
        q += __shfl_xor_sync(0xffffffffu, q, o);
    }
    __shared__ float shs[4], shq[4];
    if ((tid & 31) == 0) { shs[tid >> 5] = s; shq[tid >> 5] = q; }
    __syncthreads();
    s = shs[0] + shs[1] + shs[2] + shs[3];
    q = shq[0] + shq[1] + shq[2] + shq[3];
    const float mu  = s * (1.f / CDIM);
    const float var = q * (1.f / CDIM) - mu * mu;
    const float rr  = rsqrtf(var + 1e-5f);
    float4 vg  = *reinterpret_cast<const float4*>(g + tid * 4);
    float4 vbe = *reinterpret_cast<const float4*>(be + tid * 4);
    float4 o4;
    o4.x = (x0 - mu) * rr * vg.x + vbe.x;
    o4.y = (x1 - mu) * rr * vg.y + vbe.y;
    o4.z = (x2 - mu) * rr * vg.z + vbe.z;
    o4.w = (x3 - mu) * rr * vg.w + vbe.w;
    *reinterpret_cast<float4*>(out + base + tid * 4) = o4;
}

// =====================================================================
// Row softmax over length n (n = CNT*256). grid = (n_rows, n_heads).
// =====================================================================
template <int CNT>
__global__ void __launch_bounds__(256) softmax_kernel(float* __restrict__ S, int n)
{
    float* row = S + ((long long)blockIdx.y * n + blockIdx.x) * n;
    const int tid = threadIdx.x;
    float vals[CNT];
#pragma unroll
    for (int t = 0; t < CNT; t++) vals[t] = row[tid + t * 256];
    float m = -1e30f;
#pragma unroll
    for (int t = 0; t < CNT; t++) m = fmaxf(m, vals[t]);
    __shared__ float sh[8];
#pragma unroll
    for (int o = 16; o; o >>= 1) m = fmaxf(m, __shfl_xor_sync(0xffffffffu, m, o));
    if ((tid & 31) == 0) sh[tid >> 5] = m;
    __syncthreads();
    float mm = sh[0];
#pragma unroll
    for (int w = 1; w < 8; w++) mm = fmaxf(mm, sh[w]);
    float s = 0.f;
#pragma unroll
    for (int t = 0; t < CNT; t++) { vals[t] = expf(vals[t] - mm); s += vals[t]; }
    __syncthreads();
#pragma unroll
    for (int o = 16; o; o >>= 1) s += __shfl_xor_sync(0xffffffffu, s, o);
    if ((tid & 31) == 0) sh[tid >> 5] = s;
    __syncthreads();
    float tot = 0.f;
#pragma unroll
    for (int w = 0; w < 8; w++) tot += sh[w];
    const float inv = 1.f / tot;
#pragma unroll
    for (int t = 0; t < CNT; t++) row[tid + t * 256] = vals[t] * inv;
}

// =====================================================================
// Host-side launch helper
// =====================================================================
template <int MODE, bool TB>
static inline void launch_mma(const float* X, const float* W,
                              const float* bias, const float* res, const float* rm,
                              float* Y, int M, int N, int K,
                              int ldx, int ldw, int ldy,
                              long long sX = 0, long long sW = 0, long long sY = 0,
                              int batch = 1, float alpha = 1.f)
{
    dim3 grid((M + 127) / 128, (N + 63) / 64, batch);
    mma_gemm_kernel<MODE, TB><<<grid, 256>>>(
        X, W, bias, res, rm, Y, M, N, K, ldx, ldw, ldy, sX, sW, sY, alpha);
}

// Cached scratch pointers (symbol addresses are stable; capture-safe).
static float *s0a, *s0b, *s1a, *s1b, *s2, *cc, *hl, *h1, *qkvp, *scp, *ao, *h2p, *fm;
static bool g_ptrs_ready = false;

static void resolve_ptrs()
{
    if (g_ptrs_ready) return;
    cudaGetSymbolAddress((void**)&s0a, g_s0a);
    cudaGetSymbolAddress((void**)&s0b, g_s0b);
    cudaGetSymbolAddress((void**)&s1a, g_s1a);
    cudaGetSymbolAddress((void**)&s1b, g_s1b);
    cudaGetSymbolAddress((void**)&s2,  g_s2);
    cudaGetSymbolAddress((void**)&cc,  g_concat);
    cudaGetSymbolAddress((void**)&hl,  g_hlocal);
    cudaGetSymbolAddress((void**)&h1,  g_h1);
    cudaGetSymbolAddress((void**)&qkvp, g_qkv);
    cudaGetSymbolAddress((void**)&scp,  g_scores);
    cudaGetSymbolAddress((void**)&ao,  g_attno);
    cudaGetSymbolAddress((void**)&h2p, g_h2);
    cudaGetSymbolAddress((void**)&fm,  g_ffnmid);
    g_ptrs_ready = true;
}

extern "C" void kernel_launch(void* const* d_in, const int* in_sizes, int n_in,
                              void* d_out, int out_size)
{
    (void)in_sizes; (void)n_in; (void)out_size;
    const float* feats0  = (const float*)d_in[0];
    const float* feats1  = (const float*)d_in[1];
    const float* feats2  = (const float*)d_in[2];
    const float* nmask0  = (const float*)d_in[3];
    const float* nmask1  = (const float*)d_in[4];
    const float* nmask2  = (const float*)d_in[5];
    const int*   nbmask0 = (const int*)d_in[6];
    const int*   nbmask1 = (const int*)d_in[7];
    const float* emb_w   = (const float*)d_in[8];
    const float* emb_b   = (const float*)d_in[9];
    const float* sage_w  = (const float*)d_in[10];
    const float* sage_b  = (const float*)d_in[11];
    const float* qkv_w   = (const float*)d_in[12];
    const float* qkv_b   = (const float*)d_in[13];
    const float* out_w   = (const float*)d_in[14];
    const float* out_b   = (const float*)d_in[15];
    const float* n1_g    = (const float*)d_in[16];
    const float* n1_b    = (const float*)d_in[17];
    const float* n2_g    = (const float*)d_in[18];
    const float* n2_b    = (const float*)d_in[19];
    const float* ffn_w1  = (const float*)d_in[20];
    const float* ffn_b1  = (const float*)d_in[21];
    const float* ffn_w2  = (const float*)d_in[22];
    const float* ffn_b2  = (const float*)d_in[23];
    const float* cls_w   = (const float*)d_in[24];
    const float* cls_b   = (const float*)d_in[25];
    float* out = (float*)d_out;

    resolve_ptrs();

    // ---- embeddings: state_d = (feats_d @ emb_w^T + emb_b) * nmask_d ----
    launch_mma<1, true>(feats2, emb_w, emb_b, nullptr, nmask2, s2,
                        N2, CDIM, INDIM, INDIM, INDIM, CDIM);
    launch_mma<1, true>(feats1, emb_w, emb_b, nullptr, nmask1, s1a,
                        N1, CDIM, INDIM, INDIM, INDIM, CDIM);
    launch_mma<1, true>(feats0, emb_w, emb_b, nullptr, nmask0, s0a,
                        N0, CDIM, INDIM, INDIM, INDIM, CDIM);

    // (li, n, sf, child, out, nbm, nmask) — ping-pong reproduces prev-snapshot
    struct Step { int li, n; float *sf, *child, *outb; const int* nbm; const float* nm; };
    Step steps[3] = {
        {0, N1, s1a, s2,  s1b, nbmask1, nmask1},
        {0, N0, s0a, s1a, s0b, nbmask0, nmask0},
        {1, N0, s0b, s1b, s0a, nbmask0, nmask0},
    };

    const float scale = 1.f / sqrtf((float)DHEAD);

    for (int si = 0; si < 3; si++) {
        const Step& st = steps[si];
        const int li = st.li, n = st.n;
        const float* sw  = sage_w + (long long)li * CDIM * 2 * CDIM;
        const float* sb  = sage_b + li * CDIM;
        const float* qw  = qkv_w  + (long long)li * 3 * CDIM * CDIM;
        const float* qb  = qkv_b  + li * 3 * CDIM;
        const float* ow  = out_w  + (long long)li * CDIM * CDIM;
        const float* ob  = out_b  + li * CDIM;
        const float* g1  = n1_g + li * CDIM, *b1 = n1_b + li * CDIM;
        const float* g2  = n2_g + li * CDIM, *b2 = n2_b + li * CDIM;
        const float* fw1 = ffn_w1 + (long long)li * 2 * CDIM * CDIM;
        const float* fb1 = ffn_b1 + li * 2 * CDIM;
        const float* fw2 = ffn_w2 + (long long)li * CDIM * 2 * CDIM;
        const float* fb2 = ffn_b2 + li * CDIM;

        // 1) masked-mean aggregate + concat  -> cc [n, 1024]
        agg_concat_kernel<<<n, 128>>>(cc, st.sf, st.child, st.nbm);
        // 2) h_local = cc @ sage_w^T + sage_b
        launch_mma<0, true>(cc, sw, sb, nullptr, nullptr, hl,
                            n, CDIM, 2 * CDIM, 2 * CDIM, 2 * CDIM, CDIM);
        // 3) h1 = LN(sf + h_local)
        ln_res_kernel<<<n, 128>>>(h1, st.sf, hl, g1, b1);
        // 4) qkv = h1 @ qkv_w^T + qkv_b
        launch_mma<0, true>(h1, qw, qb, nullptr, nullptr, qkvp,
                            n, 3 * CDIM, CDIM, CDIM, CDIM, 3 * CDIM);
        // 5) scores[h] = scale * Q_h @ K_h^T   (batched over 4 heads)
        launch_mma<2, true>(qkvp, qkvp + CDIM, nullptr, nullptr, nullptr, scp,
                            n, n, DHEAD, 3 * CDIM, 3 * CDIM, n,
                            DHEAD, DHEAD, (long long)n * n, NHEAD, scale);
        // 6) softmax over keys
        if (n == N1) softmax_kernel<16><<<dim3(N1, NHEAD), 256>>>(scp, n);
        else         softmax_kernel<1><<<dim3(N0, NHEAD), 256>>>(scp, n);
        // 7) O_h = A_h @ V_h  (NN GEMM, batched over heads; head-interleaved out)
        launch_mma<2, false>(scp, qkvp + 2 * CDIM, nullptr, nullptr, nullptr, ao,
                             n, DHEAD, n, n, 3 * CDIM, CDIM,
                             (long long)n * n, DHEAD, DHEAD, NHEAD, 1.f);
        // 8) proj = O @ out_w^T + out_b
        launch_mma<0, true>(ao, ow, ob, nullptr, nullptr, hl,
                            n, CDIM, CDIM, CDIM, CDIM, CDIM);
        // 9) h2 = LN(h1 + proj)
        ln_res_kernel<<<n, 128>>>(h2p, h1, hl, g2, b2);
        // 10) mid = relu(h2 @ ffn_w1^T + ffn_b1)
        launch_mma<3, true>(h2p, fw1, fb1, nullptr, nullptr, fm,
                            n, 2 * CDIM, CDIM, CDIM, CDIM, 2 * CDIM);
        // 11) state = (h2 + mid @ ffn_w2^T + ffn_b2) * nmask
        launch_mma<4, true>(fm, fw2, fb2, h2p, st.nm, st.outb,
                            n, CDIM, 2 * CDIM, 2 * CDIM, 2 * CDIM, CDIM);
    }

    // ---- classifier: out = state0 @ cls_w^T + cls_b ----
    launch_mma<0, true>(s0a, cls_w, cls_b, nullptr, nullptr, out,
                        N0, NCLS, CDIM, CDIM, CDIM, NCLS);
}

// round 10
// speedup vs baseline: 1.7409x; 1.1031x over previous
#include <cuda_runtime.h>
#include <cuda_bf16.h>
#include <math.h>

// ---------------- problem dims ----------------
#define CDIM 512
#define INDIM 256
#define NHEAD 4
#define DHEAD 128
#define FANOUT 16
#define NCLS 47
#define N0 256
#define N1 4096
#define N2 65536
#define NL 2

typedef __nv_bfloat16 bf16;

// ---------------- fp32 scratch ----------------
__device__ float g_s0a[N0 * CDIM];
__device__ float g_s0b[N0 * CDIM];
__device__ float g_s1a[N1 * CDIM];
__device__ float g_s1b[N1 * CDIM];
__device__ float g_s2[(long long)N2 * CDIM];
__device__ float g_hlocal[N1 * CDIM];
__device__ float g_h1[N1 * CDIM];
__device__ float g_h2[N1 * CDIM];
__device__ float g_scores[(long long)NHEAD * N1 * N1];   // 268 MB fp32 (QK out)

// ---------------- split-bf16 scratch (hi/lo) ----------------
__device__ bf16 g_f2h[(long long)N2 * INDIM], g_f2l[(long long)N2 * INDIM];
__device__ bf16 g_f1h[N1 * INDIM], g_f1l[N1 * INDIM];
__device__ bf16 g_f0h[N0 * INDIM], g_f0l[N0 * INDIM];
__device__ bf16 g_wembh[CDIM * INDIM], g_wembl[CDIM * INDIM];
__device__ bf16 g_wsageh[NL * CDIM * 2 * CDIM], g_wsagel[NL * CDIM * 2 * CDIM];
__device__ bf16 g_wqkvh[NL * 3 * CDIM * CDIM], g_wqkvl[NL * 3 * CDIM * CDIM];
__device__ bf16 g_wouth[NL * CDIM * CDIM], g_woutl[NL * CDIM * CDIM];
__device__ bf16 g_wf1h[NL * 2 * CDIM * CDIM], g_wf1l[NL * 2 * CDIM * CDIM];
__device__ bf16 g_wf2h[NL * CDIM * 2 * CDIM], g_wf2l[NL * CDIM * 2 * CDIM];
__device__ bf16 g_wclsh[NCLS * CDIM + 64], g_wclsl[NCLS * CDIM + 64];
__device__ bf16 g_cch[N1 * 2 * CDIM], g_ccl[N1 * 2 * CDIM];
__device__ bf16 g_h1h[N1 * CDIM], g_h1l[N1 * CDIM];
__device__ bf16 g_h2h[N1 * CDIM], g_h2l[N1 * CDIM];
__device__ bf16 g_qkvh[N1 * 3 * CDIM], g_qkvl[N1 * 3 * CDIM];
__device__ bf16 g_sch[(long long)NHEAD * N1 * N1], g_scl[(long long)NHEAD * N1 * N1];
__device__ bf16 g_aoh[N1 * CDIM], g_aol[N1 * CDIM];
__device__ bf16 g_fmh[N1 * 2 * CDIM], g_fml[N1 * 2 * CDIM];
__device__ bf16 g_s0h[N0 * CDIM], g_s0l[N0 * CDIM];

// =====================================================================
// split helpers
// =====================================================================
__device__ __forceinline__ void split1(float x, bf16& h, bf16& l)
{
    h = __float2bfloat16(x);
    l = __float2bfloat16(x - __bfloat162float(h));
}

// grid-stride fp32 -> (hi, lo) bf16. n4 = element_count / 4.
__global__ void split_kernel(const float* __restrict__ src,
                             bf16* __restrict__ h, bf16* __restrict__ l, long long n4)
{
    for (long long i = blockIdx.x * (long long)blockDim.x + threadIdx.x;
         i < n4; i += (long long)gridDim.x * blockDim.x) {
        float4 v = reinterpret_cast<const float4*>(src)[i];
        union { bf16 b[4]; uint2 u; } uh, ul;
        split1(v.x, uh.b[0], ul.b[0]);
        split1(v.y, uh.b[1], ul.b[1]);
        split1(v.z, uh.b[2], ul.b[2]);
        split1(v.w, uh.b[3], ul.b[3]);
        reinterpret_cast<uint2*>(h)[i] = uh.u;
        reinterpret_cast<uint2*>(l)[i] = ul.u;
    }
}

// =====================================================================
// Tensor-core GEMM (mma.sync bf16, 3-pass split) on pre-split inputs.
//   Y = op( A[M,K] * B )  B: [N,K] (TRANSB) or [K,N] (!TRANSB)
// Block 128x64x32, 256 thr, 8 warps (4x2), warp tile 32x32.
// MODE: 0 +bias | 1 (+bias)*rowmask | 2 *alpha | 3 relu(+bias)
//       4 (res + v + bias)*rowmask
// SPLIT_OUT: write (Yh, Yl) bf16 instead of fp32 Y.
// NN path requires full BN-vector columns (true at all call sites: N=DHEAD).
// =====================================================================
__device__ __forceinline__ void mma16816(float* c, const unsigned* a, const unsigned* b)
{
    asm volatile(
        "mma.sync.aligned.m16n8k16.row.col.f32.bf16.bf16.f32 "
        "{%0,%1,%2,%3}, {%4,%5,%6,%7}, {%8,%9}, {%0,%1,%2,%3};\n"
        : "+f"(c[0]), "+f"(c[1]), "+f"(c[2]), "+f"(c[3])
        : "r"(a[0]), "r"(a[1]), "r"(a[2]), "r"(a[3]), "r"(b[0]), "r"(b[1]));
}

template <int MODE, bool TRANSB, bool SPLIT_OUT>
__global__ void __launch_bounds__(256) mma_gemm_kernel(
    const bf16* __restrict__ Ahg, const bf16* __restrict__ Alg,
    const bf16* __restrict__ Bhg, const bf16* __restrict__ Blg,
    const float* __restrict__ bias, const float* __restrict__ res,
    const float* __restrict__ rowmask,
    float* __restrict__ Yg, bf16* __restrict__ Yhg, bf16* __restrict__ Ylg,
    int M, int N, int K, int ldx, int ldw, int ldy,
    long long sX, long long sW, long long sY, float alpha)
{
    constexpr int BM = 128, BN = 64, BK = 32;
    constexpr int LDA = 40, LDB = 40;

    const bf16* Ah = Ahg + (long long)blockIdx.z * sX;
    const bf16* Al = Alg + (long long)blockIdx.z * sX;
    const bf16* Bh = Bhg + (long long)blockIdx.z * sW;
    const bf16* Bl = Blg + (long long)blockIdx.z * sW;
    float* Y  = Yg  ? Yg  + (long long)blockIdx.z * sY : nullptr;
    bf16*  Yh = Yhg ? Yhg + (long long)blockIdx.z * sY : nullptr;
    bf16*  Yl = Ylg ? Ylg + (long long)blockIdx.z * sY : nullptr;

    __shared__ alignas(16) bf16 sAh[BM * LDA], sAl[BM * LDA];
    __shared__ alignas(16) bf16 sBh[BN * LDB], sBl[BN * LDB];

    const int tid  = threadIdx.x;
    const int warp = tid >> 5;
    const int lane = tid & 31;
    const int wm   = warp & 3;
    const int wn   = warp >> 2;
    const int m0   = blockIdx.x * BM;
    const int n0   = blockIdx.y * BN;
    const int r    = lane >> 2;
    const int c2   = (lane & 3) * 2;

    float acc[2][4][4];
#pragma unroll
    for (int mt = 0; mt < 2; mt++)
#pragma unroll
        for (int nt = 0; nt < 4; nt++)
#pragma unroll
            for (int e = 0; e < 4; e++) acc[mt][nt][e] = 0.f;

    const uint4 z16 = make_uint4(0u, 0u, 0u, 0u);

    for (int k0 = 0; k0 < K; k0 += BK) {
        // ---- A tile [BM x BK]: 512 x uint4 (8 bf16 each) ----
#pragma unroll
        for (int it = 0; it < 2; it++) {
            int idx = tid + it * 256;
            int row = idx >> 2;
            int q   = (idx & 3) * 8;
            uint4 vh = z16, vl = z16;
            if ((m0 + row) < M) {
                const long long o = (long long)(m0 + row) * ldx + k0 + q;
                vh = *reinterpret_cast<const uint4*>(Ah + o);
                vl = *reinterpret_cast<const uint4*>(Al + o);
            }
            *reinterpret_cast<uint4*>(&sAh[row * LDA + q]) = vh;
            *reinterpret_cast<uint4*>(&sAl[row * LDA + q]) = vl;
        }
        // ---- B tile -> [n][k] layout ----
        if (TRANSB) {
            int row = tid >> 2;
            int q   = (tid & 3) * 8;
            uint4 vh = z16, vl = z16;
            if ((n0 + row) < N) {
                const long long o = (long long)(n0 + row) * ldw + k0 + q;
                vh = *reinterpret_cast<const uint4*>(Bh + o);
                vl = *reinterpret_cast<const uint4*>(Bl + o);
            }
            *reinterpret_cast<uint4*>(&sBh[row * LDB + q]) = vh;
            *reinterpret_cast<uint4*>(&sBl[row * LDB + q]) = vl;
        } else {
            int kk = tid >> 3;              // 0..31 (k within tile)
            int nq = (tid & 7) * 8;         // 0..56 (n offset)
            uint4 vh = z16, vl = z16;
            if ((n0 + nq + 7) < N) {        // all NN sites: N=128, always true
                const long long o = (long long)(k0 + kk) * ldw + n0 + nq;
                vh = *reinterpret_cast<const uint4*>(Bh + o);
                vl = *reinterpret_cast<const uint4*>(Bl + o);
            }
            const bf16* ph = reinterpret_cast<const bf16*>(&vh);
            const bf16* pl = reinterpret_cast<const bf16*>(&vl);
#pragma unroll
            for (int e = 0; e < 8; e++) {
                sBh[(nq + e) * LDB + kk] = ph[e];
                sBl[(nq + e) * LDB + kk] = pl[e];
            }
        }
        __syncthreads();

#pragma unroll
        for (int ks = 0; ks < 2; ks++) {
            const int koff = ks * 16;
            unsigned ah[2][4], al[2][4], bh[4][2], bl[4][2];
#pragma unroll
            for (int mt = 0; mt < 2; mt++) {
                const int rb = (wm * 32 + mt * 16 + r) * LDA + koff + c2;
                ah[mt][0] = *reinterpret_cast<const unsigned*>(&sAh[rb]);
                ah[mt][1] = *reinterpret_cast<const unsigned*>(&sAh[rb + 8 * LDA]);
                ah[mt][2] = *reinterpret_cast<const unsigned*>(&sAh[rb + 8]);
                ah[mt][3] = *reinterpret_cast<const unsigned*>(&sAh[rb + 8 * LDA + 8]);
                al[mt][0] = *reinterpret_cast<const unsigned*>(&sAl[rb]);
                al[mt][1] = *reinterpret_cast<const unsigned*>(&sAl[rb + 8 * LDA]);
                al[mt][2] = *reinterpret_cast<const unsigned*>(&sAl[rb + 8]);
                al[mt][3] = *reinterpret_cast<const unsigned*>(&sAl[rb + 8 * LDA + 8]);
            }
#pragma unroll
            for (int nt = 0; nt < 4; nt++) {
                const int cb = (wn * 32 + nt * 8 + r) * LDB + koff + c2;
                bh[nt][0] = *reinterpret_cast<const unsigned*>(&sBh[cb]);
                bh[nt][1] = *reinterpret_cast<const unsigned*>(&sBh[cb + 8]);
                bl[nt][0] = *reinterpret_cast<const unsigned*>(&sBl[cb]);
                bl[nt][1] = *reinterpret_cast<const unsigned*>(&sBl[cb + 8]);
            }
#pragma unroll
            for (int mt = 0; mt < 2; mt++)
#pragma unroll
                for (int nt = 0; nt < 4; nt++) {
                    mma16816(acc[mt][nt], ah[mt], bh[nt]);
                    mma16816(acc[mt][nt], ah[mt], bl[nt]);
                    mma16816(acc[mt][nt], al[mt], bh[nt]);
                }
        }
        __syncthreads();
    }

    // ---- epilogue ----
#pragma unroll
    for (int mt = 0; mt < 2; mt++) {
#pragma unroll
        for (int nt = 0; nt < 4; nt++) {
#pragma unroll
            for (int e = 0; e < 4; e++) {
                const int gr = m0 + wm * 32 + mt * 16 + r + (e >= 2 ? 8 : 0);
                const int gc = n0 + wn * 32 + nt * 8 + c2 + (e & 1);
                if (gr >= M || gc >= N) continue;
                float v = acc[mt][nt][e];
                if (MODE == 0)      v = v + bias[gc];
                else if (MODE == 1) v = (v + bias[gc]) * rowmask[gr];
                else if (MODE == 2) v = v * alpha;
                else if (MODE == 3) v = fmaxf(v + bias[gc], 0.f);
                else if (MODE == 4) v = (res[(long long)gr * ldy + gc] + v + bias[gc]) * rowmask[gr];
                const long long off = (long long)gr * ldy + gc;
                if (SPLIT_OUT) {
                    bf16 h, l; split1(v, h, l);
                    Yh[off] = h; Yl[off] = l;
                } else {
                    Y[off] = v;
                }
            }
        }
    }
}

// =====================================================================
// Masked-mean aggregation + concat -> split-bf16 cc (GEMM input only)
// =====================================================================
__global__ void __launch_bounds__(128) agg_concat_kernel(
    bf16* __restrict__ outh, bf16* __restrict__ outl,
    const float* __restrict__ sf, const float* __restrict__ child,
    const int* __restrict__ nbm)
{
    const int i = blockIdx.x;
    const int tid = threadIdx.x;
    __shared__ float mk[FANOUT];
    __shared__ float invd;
    if (tid < FANOUT) mk[tid] = (float)nbm[i * FANOUT + tid];
    __syncthreads();
    if (tid == 0) {
        float s = 0.f;
#pragma unroll
        for (int f = 0; f < FANOUT; f++) s += mk[f];
        invd = 1.f / fmaxf(s, 1.f);
    }
    __syncthreads();
    const float dinv = invd;
    const long long ob = (long long)i * (2 * CDIM) + tid * 4;

    float4 v0 = *reinterpret_cast<const float4*>(sf + (long long)i * CDIM + tid * 4);
    union { bf16 b[4]; uint2 u; } uh, ul;
    split1(v0.x, uh.b[0], ul.b[0]); split1(v0.y, uh.b[1], ul.b[1]);
    split1(v0.z, uh.b[2], ul.b[2]); split1(v0.w, uh.b[3], ul.b[3]);
    *reinterpret_cast<uint2*>(outh + ob) = uh.u;
    *reinterpret_cast<uint2*>(outl + ob) = ul.u;

    float4 acc = make_float4(0.f, 0.f, 0.f, 0.f);
    const float* cb = child + (long long)i * FANOUT * CDIM + tid * 4;
#pragma unroll
    for (int f = 0; f < FANOUT; f++) {
        float4 v = *reinterpret_cast<const float4*>(cb + f * CDIM);
        float w = mk[f];
        acc.x += v.x * w; acc.y += v.y * w; acc.z += v.z * w; acc.w += v.w * w;
    }
    acc.x *= dinv; acc.y *= dinv; acc.z *= dinv; acc.w *= dinv;
    split1(acc.x, uh.b[0], ul.b[0]); split1(acc.y, uh.b[1], ul.b[1]);
    split1(acc.z, uh.b[2], ul.b[2]); split1(acc.w, uh.b[3], ul.b[3]);
    *reinterpret_cast<uint2*>(outh + ob + CDIM) = uh.u;
    *reinterpret_cast<uint2*>(outl + ob + CDIM) = ul.u;
}

// =====================================================================
// Residual + LayerNorm: fp32 out + fused split-bf16 out
// =====================================================================
__global__ void __launch_bounds__(128) ln_res_kernel(
    float* __restrict__ out, bf16* __restrict__ outh, bf16* __restrict__ outl,
    const float* __restrict__ a, const float* __restrict__ b,
    const float* __restrict__ g, const float* __restrict__ be)
{
    const long long base = (long long)blockIdx.x * CDIM;
    const int tid = threadIdx.x;
    float4 va = *reinterpret_cast<const float4*>(a + base + tid * 4);
    float4 vb = *reinterpret_cast<const float4*>(b + base + tid * 4);
    float x0 = va.x + vb.x, x1 = va.y + vb.y, x2 = va.z + vb.z, x3 = va.w + vb.w;
    float s = x0 + x1 + x2 + x3;
    float q = x0 * x0 + x1 * x1 + x2 * x2 + x3 * x3;
#pragma unroll
    for (int o = 16; o; o >>= 1) {
        s += __shfl_xor_sync(0xffffffffu, s, o);
        q += __shfl_xor_sync(0xffffffffu, q, o);
    }
    __shared__ float shs[4], shq[4];
    if ((tid & 31) == 0) { shs[tid >> 5] = s; shq[tid >> 5] = q; }
    __syncthreads();
    s = shs[0] + shs[1] + shs[2] + shs[3];
    q = shq[0] + shq[1] + shq[2] + shq[3];
    const float mu  = s * (1.f / CDIM);
    const float var = q * (1.f / CDIM) - mu * mu;
    const float rr  = rsqrtf(var + 1e-5f);
    float4 vg  = *reinterpret_cast<const float4*>(g + tid * 4);
    float4 vbe = *reinterpret_cast<const float4*>(be + tid * 4);
    float4 o4;
    o4.x = (x0 - mu) * rr * vg.x + vbe.x;
    o4.y = (x1 - mu) * rr * vg.y + vbe.y;
    o4.z = (x2 - mu) * rr * vg.z + vbe.z;
    o4.w = (x3 - mu) * rr * vg.w + vbe.w;
    *reinterpret_cast<float4*>(out + base + tid * 4) = o4;
    union { bf16 bb[4]; uint2 u; } uh, ul;
    split1(o4.x, uh.bb[0], ul.bb[0]); split1(o4.y, uh.bb[1], ul.bb[1]);
    split1(o4.z, uh.bb[2], ul.bb[2]); split1(o4.w, uh.bb[3], ul.bb[3]);
    *reinterpret_cast<uint2*>(outh + base + tid * 4) = uh.u;
    *reinterpret_cast<uint2*>(outl + base + tid * 4) = ul.u;
}

// =====================================================================
// Row softmax; writes split-bf16 probabilities (PV GEMM input) directly.
// =====================================================================
template <int CNT>
__global__ void __launch_bounds__(256) softmax_kernel(
    const float* __restrict__ S, bf16* __restrict__ Sh, bf16* __restrict__ Sl, int n)
{
    const long long rb = ((long long)blockIdx.y * n + blockIdx.x) * n;
    const float* row = S + rb;
    const int tid = threadIdx.x;
    float vals[CNT];
#pragma unroll
    for (int t = 0; t < CNT; t++) vals[t] = row[tid + t * 256];
    float m = -1e30f;
#pragma unroll
    for (int t = 0; t < CNT; t++) m = fmaxf(m, vals[t]);
    __shared__ float sh[8];
#pragma unroll
    for (int o = 16; o; o >>= 1) m = fmaxf(m, __shfl_xor_sync(0xffffffffu, m, o));
    if ((tid & 31) == 0) sh[tid >> 5] = m;
    __syncthreads();
    float mm = sh[0];
#pragma unroll
    for (int w = 1; w < 8; w++) mm = fmaxf(mm, sh[w]);
    float s = 0.f;
#pragma unroll
    for (int t = 0; t < CNT; t++) { vals[t] = expf(vals[t] - mm); s += vals[t]; }
    __syncthreads();
#pragma unroll
    for (int o = 16; o; o >>= 1) s += __shfl_xor_sync(0xffffffffu, s, o);
    if ((tid & 31) == 0) sh[tid >> 5] = s;
    __syncthreads();
    float tot = 0.f;
#pragma unroll
    for (int w = 0; w < 8; w++) tot += sh[w];
    const float inv = 1.f / tot;
#pragma unroll
    for (int t = 0; t < CNT; t++) {
        float p = vals[t] * inv;
        bf16 h, l; split1(p, h, l);
        Sh[rb + tid + t * 256] = h;
        Sl[rb + tid + t * 256] = l;
    }
}

// =====================================================================
// Host-side helpers
// =====================================================================
template <int MODE, bool TB, bool SO>
static inline void launch_mma(const bf16* Ah, const bf16* Al,
                              const bf16* Bh, const bf16* Bl,
                              const float* bias, const float* res, const float* rm,
                              float* Y, bf16* Yh, bf16* Yl,
                              int M, int N, int K, int ldx, int ldw, int ldy,
                              long long sX = 0, long long sW = 0, long long sY = 0,
                              int batch = 1, float alpha = 1.f)
{
    dim3 grid((M + 127) / 128, (N + 63) / 64, batch);
    mma_gemm_kernel<MODE, TB, SO><<<grid, 256>>>(
        Ah, Al, Bh, Bl, bias, res, rm, Y, Yh, Yl,
        M, N, K, ldx, ldw, ldy, sX, sW, sY, alpha);
}

static inline void launch_split(const float* s, bf16* h, bf16* l, long long cnt)
{
    long long n4 = cnt / 4;
    int grid = (int)((n4 + 255) / 256);
    if (grid > 4096) grid = 4096;
    split_kernel<<<grid, 256>>>(s, h, l, n4);
}

// Cached scratch pointers
static float *s0a, *s0b, *s1a, *s1b, *s2, *hl, *h1, *h2p, *scp;
static bf16 *f2h, *f2l, *f1h, *f1l, *f0h, *f0l;
static bf16 *wembh, *wembl, *wsageh, *wsagel, *wqkvh, *wqkvl, *wouth, *woutl;
static bf16 *wf1h, *wf1l, *wf2h, *wf2l, *wclsh, *wclsl;
static bf16 *cch, *ccl, *h1h, *h1l, *h2h, *h2l, *qkvh, *qkvl;
static bf16 *sch, *scl, *aoh, *aol, *fmh, *fml, *s0h, *s0l;
static bool g_ptrs_ready = false;

#define SYM(p, s) cudaGetSymbolAddress((void**)&(p), s)

static void resolve_ptrs()
{
    if (g_ptrs_ready) return;
    SYM(s0a, g_s0a); SYM(s0b, g_s0b); SYM(s1a, g_s1a); SYM(s1b, g_s1b);
    SYM(s2, g_s2); SYM(hl, g_hlocal); SYM(h1, g_h1); SYM(h2p, g_h2); SYM(scp, g_scores);
    SYM(f2h, g_f2h); SYM(f2l, g_f2l); SYM(f1h, g_f1h); SYM(f1l, g_f1l);
    SYM(f0h, g_f0h); SYM(f0l, g_f0l);
    SYM(wembh, g_wembh); SYM(wembl, g_wembl);
    SYM(wsageh, g_wsageh); SYM(wsagel, g_wsagel);
    SYM(wqkvh, g_wqkvh); SYM(wqkvl, g_wqkvl);
    SYM(wouth, g_wouth); SYM(woutl, g_woutl);
    SYM(wf1h, g_wf1h); SYM(wf1l, g_wf1l);
    SYM(wf2h, g_wf2h); SYM(wf2l, g_wf2l);
    SYM(wclsh, g_wclsh); SYM(wclsl, g_wclsl);
    SYM(cch, g_cch); SYM(ccl, g_ccl);
    SYM(h1h, g_h1h); SYM(h1l, g_h1l);
    SYM(h2h, g_h2h); SYM(h2l, g_h2l);
    SYM(qkvh, g_qkvh); SYM(qkvl, g_qkvl);
    SYM(sch, g_sch); SYM(scl, g_scl);
    SYM(aoh, g_aoh); SYM(aol, g_aol);
    SYM(fmh, g_fmh); SYM(fml, g_fml);
    SYM(s0h, g_s0h); SYM(s0l, g_s0l);
    g_ptrs_ready = true;
}

extern "C" void kernel_launch(void* const* d_in, const int* in_sizes, int n_in,
                              void* d_out, int out_size)
{
    (void)in_sizes; (void)n_in; (void)out_size;
    const float* feats0  = (const float*)d_in[0];
    const float* feats1  = (const float*)d_in[1];
    const float* feats2  = (const float*)d_in[2];
    const float* nmask0  = (const float*)d_in[3];
    const float* nmask1  = (const float*)d_in[4];
    const float* nmask2  = (const float*)d_in[5];
    const int*   nbmask0 = (const int*)d_in[6];
    const int*   nbmask1 = (const int*)d_in[7];
    const float* emb_w   = (const float*)d_in[8];
    const float* emb_b   = (const float*)d_in[9];
    const float* sage_w  = (const float*)d_in[10];
    const float* sage_b  = (const float*)d_in[11];
    const float* qkv_w   = (const float*)d_in[12];
    const float* qkv_b   = (const float*)d_in[13];
    const float* out_w   = (const float*)d_in[14];
    const float* out_b   = (const float*)d_in[15];
    const float* n1_g    = (const float*)d_in[16];
    const float* n1_b    = (const float*)d_in[17];
    const float* n2_g    = (const float*)d_in[18];
    const float* n2_b    = (const float*)d_in[19];
    const float* ffn_w1  = (const float*)d_in[20];
    const float* ffn_b1  = (const float*)d_in[21];
    const float* ffn_w2  = (const float*)d_in[22];
    const float* ffn_b2  = (const float*)d_in[23];
    const float* cls_w   = (const float*)d_in[24];
    const float* cls_b   = (const float*)d_in[25];
    float* out = (float*)d_out;

    resolve_ptrs();

    // ---- pre-split inputs & weights (bf16 hi/lo) ----
    launch_split(feats2, f2h, f2l, (long long)N2 * INDIM);
    launch_split(feats1, f1h, f1l, (long long)N1 * INDIM);
    launch_split(feats0, f0h, f0l, (long long)N0 * INDIM);
    launch_split(emb_w,  wembh, wembl, (long long)CDIM * INDIM);
    launch_split(sage_w, wsageh, wsagel, (long long)NL * CDIM * 2 * CDIM);
    launch_split(qkv_w,  wqkvh, wqkvl, (long long)NL * 3 * CDIM * CDIM);
    launch_split(out_w,  wouth, woutl, (long long)NL * CDIM * CDIM);
    launch_split(ffn_w1, wf1h, wf1l, (long long)NL * 2 * CDIM * CDIM);
    launch_split(ffn_w2, wf2h, wf2l, (long long)NL * CDIM * 2 * CDIM);
    launch_split(cls_w,  wclsh, wclsl, (long long)NCLS * CDIM);  // 24064 % 4 == 0

    // ---- embeddings: state_d = (feats_d @ emb_w^T + emb_b) * nmask_d ----
    launch_mma<1, true, false>(f2h, f2l, wembh, wembl, emb_b, nullptr, nmask2,
                               s2, nullptr, nullptr, N2, CDIM, INDIM, INDIM, INDIM, CDIM);
    launch_mma<1, true, false>(f1h, f1l, wembh, wembl, emb_b, nullptr, nmask1,
                               s1a, nullptr, nullptr, N1, CDIM, INDIM, INDIM, INDIM, CDIM);
    launch_mma<1, true, false>(f0h, f0l, wembh, wembl, emb_b, nullptr, nmask0,
                               s0a, nullptr, nullptr, N0, CDIM, INDIM, INDIM, INDIM, CDIM);

    struct Step { int li, n; float *sf, *child, *outb; const int* nbm; const float* nm; bool last; };
    Step steps[3] = {
        {0, N1, s1a, s2,  s1b, nbmask1, nmask1, false},
        {0, N0, s0a, s1a, s0b, nbmask0, nmask0, false},
        {1, N0, s0b, s1b, nullptr, nbmask0, nmask0, true},  // last: split out -> s0h/s0l
    };

    const float scale = 1.f / sqrtf((float)DHEAD);

    for (int si = 0; si < 3; si++) {
        const Step& st = steps[si];
        const int li = st.li, n = st.n;
        const bf16* swh = wsageh + (long long)li * CDIM * 2 * CDIM;
        const bf16* swl = wsagel + (long long)li * CDIM * 2 * CDIM;
        const float* sb = sage_b + li * CDIM;
        const bf16* qwh = wqkvh + (long long)li * 3 * CDIM * CDIM;
        const bf16* qwl = wqkvl + (long long)li * 3 * CDIM * CDIM;
        const float* qb = qkv_b + li * 3 * CDIM;
        const bf16* owh = wouth + (long long)li * CDIM * CDIM;
        const bf16* owl = woutl + (long long)li * CDIM * CDIM;
        const float* ob = out_b + li * CDIM;
        const float* g1 = n1_g + li * CDIM, *b1 = n1_b + li * CDIM;
        const float* g2 = n2_g + li * CDIM, *b2 = n2_b + li * CDIM;
        const bf16* f1wh = wf1h + (long long)li * 2 * CDIM * CDIM;
        const bf16* f1wl = wf1l + (long long)li * 2 * CDIM * CDIM;
        const float* fb1 = ffn_b1 + li * 2 * CDIM;
        const bf16* f2wh = wf2h + (long long)li * CDIM * 2 * CDIM;
        const bf16* f2wl = wf2l + (long long)li * CDIM * 2 * CDIM;
        const float* fb2 = ffn_b2 + li * CDIM;

        // 1) masked-mean aggregate + concat -> split cc [n, 1024]
        agg_concat_kernel<<<n, 128>>>(cch, ccl, st.sf, st.child, st.nbm);
        // 2) h_local = cc @ sage_w^T + sage_b   (fp32 out)
        launch_mma<0, true, false>(cch, ccl, swh, swl, sb, nullptr, nullptr,
                                   hl, nullptr, nullptr,
                                   n, CDIM, 2 * CDIM, 2 * CDIM, 2 * CDIM, CDIM);
        // 3) h1 = LN(sf + h_local)  (fp32 + split)
        ln_res_kernel<<<n, 128>>>(h1, h1h, h1l, st.sf, hl, g1, b1);
        // 4) qkv = h1 @ qkv_w^T + qkv_b  (split out)
        launch_mma<0, true, true>(h1h, h1l, qwh, qwl, qb, nullptr, nullptr,
                                  nullptr, qkvh, qkvl,
                                  n, 3 * CDIM, CDIM, CDIM, CDIM, 3 * CDIM);
        // 5) scores[h] = scale * Q_h @ K_h^T  (fp32 out; batched 4 heads)
        launch_mma<2, true, false>(qkvh, qkvl, qkvh + CDIM, qkvl + CDIM,
                                   nullptr, nullptr, nullptr,
                                   scp, nullptr, nullptr,
                                   n, n, DHEAD, 3 * CDIM, 3 * CDIM, n,
                                   DHEAD, DHEAD, (long long)n * n, NHEAD, scale);
        // 6) softmax -> split probabilities
        if (n == N1) softmax_kernel<16><<<dim3(N1, NHEAD), 256>>>(scp, sch, scl, n);
        else         softmax_kernel<1><<<dim3(N0, NHEAD), 256>>>(scp, sch, scl, n);
        // 7) O_h = P_h @ V_h  (NN, batched; split out, head-interleaved)
        launch_mma<2, false, true>(sch, scl, qkvh + 2 * CDIM, qkvl + 2 * CDIM,
                                   nullptr, nullptr, nullptr,
                                   nullptr, aoh, aol,
                                   n, DHEAD, n, n, 3 * CDIM, CDIM,
                                   (long long)n * n, DHEAD, DHEAD, NHEAD, 1.f);
        // 8) proj = O @ out_w^T + out_b  (fp32 out)
        launch_mma<0, true, false>(aoh, aol, owh, owl, ob, nullptr, nullptr,
                                   hl, nullptr, nullptr,
                                   n, CDIM, CDIM, CDIM, CDIM, CDIM);
        // 9) h2 = LN(h1 + proj)  (fp32 + split)
        ln_res_kernel<<<n, 128>>>(h2p, h2h, h2l, h1, hl, g2, b2);
        // 10) mid = relu(h2 @ ffn_w1^T + ffn_b1)  (split out)
        launch_mma<3, true, true>(h2h, h2l, f1wh, f1wl, fb1, nullptr, nullptr,
                                  nullptr, fmh, fml,
                                  n, 2 * CDIM, CDIM, CDIM, CDIM, 2 * CDIM);
        // 11) state = (h2 + mid @ ffn_w2^T + ffn_b2) * nmask
        if (st.last)
            launch_mma<4, true, true>(fmh, fml, f2wh, f2wl, fb2, h2p, st.nm,
                                      nullptr, s0h, s0l,
                                      n, CDIM, 2 * CDIM, 2 * CDIM, 2 * CDIM, CDIM);
        else
            launch_mma<4, true, false>(fmh, fml, f2wh, f2wl, fb2, h2p, st.nm,
                                       st.outb, nullptr, nullptr,
                                       n, CDIM, 2 * CDIM, 2 * CDIM, 2 * CDIM, CDIM);
    }

    // ---- classifier: out = state0 @ cls_w^T + cls_b ----
    launch_mma<0, true, false>(s0h, s0l, wclsh, wclsl, cls_b, nullptr, nullptr,
                               out, nullptr, nullptr,
                               N0, NCLS, CDIM, CDIM, CDIM, NCLS);
}

// round 11
// speedup vs baseline: 1.8918x; 1.0867x over previous
#include <cuda_runtime.h>
#include <cuda_bf16.h>
#include <math.h>

// ---------------- problem dims ----------------
#define CDIM 512
#define INDIM 256
#define NHEAD 4
#define DHEAD 128
#define FANOUT 16
#define NCLS 47
#define N0 256
#define N1 4096
#define N2 65536
#define NL 2

typedef __nv_bfloat16 bf16;

// ---------------- fp32 scratch ----------------
__device__ float g_s0a[N0 * CDIM];
__device__ float g_s0b[N0 * CDIM];
__device__ float g_s1a[N1 * CDIM];
__device__ float g_s1b[N1 * CDIM];
__device__ float g_s2[(long long)N2 * CDIM];
__device__ float g_hlocal[N1 * CDIM];
__device__ float g_h1[N1 * CDIM];
__device__ float g_h2[N1 * CDIM];
__device__ float g_scores[(long long)NHEAD * N1 * N1];   // 268 MB fp32 (QK out)

// ---------------- split-bf16 scratch (hi/lo) ----------------
__device__ bf16 g_f2h[(long long)N2 * INDIM], g_f2l[(long long)N2 * INDIM];
__device__ bf16 g_f1h[N1 * INDIM], g_f1l[N1 * INDIM];
__device__ bf16 g_f0h[N0 * INDIM], g_f0l[N0 * INDIM];
__device__ bf16 g_wembh[CDIM * INDIM], g_wembl[CDIM * INDIM];
__device__ bf16 g_wsageh[NL * CDIM * 2 * CDIM], g_wsagel[NL * CDIM * 2 * CDIM];
__device__ bf16 g_wqkvh[NL * 3 * CDIM * CDIM], g_wqkvl[NL * 3 * CDIM * CDIM];
__device__ bf16 g_wouth[NL * CDIM * CDIM], g_woutl[NL * CDIM * CDIM];
__device__ bf16 g_wf1h[NL * 2 * CDIM * CDIM], g_wf1l[NL * 2 * CDIM * CDIM];
__device__ bf16 g_wf2h[NL * CDIM * 2 * CDIM], g_wf2l[NL * CDIM * 2 * CDIM];
__device__ bf16 g_wclsh[NCLS * CDIM + 64], g_wclsl[NCLS * CDIM + 64];
__device__ bf16 g_cch[N1 * 2 * CDIM], g_ccl[N1 * 2 * CDIM];
__device__ bf16 g_h1h[N1 * CDIM], g_h1l[N1 * CDIM];
__device__ bf16 g_h2h[N1 * CDIM], g_h2l[N1 * CDIM];
__device__ bf16 g_qkvh[N1 * 3 * CDIM], g_qkvl[N1 * 3 * CDIM];
__device__ bf16 g_sch[(long long)NHEAD * N1 * N1], g_scl[(long long)NHEAD * N1 * N1];
__device__ bf16 g_vth[NHEAD * DHEAD * N1], g_vtl[NHEAD * DHEAD * N1];
__device__ bf16 g_aoh[N1 * CDIM], g_aol[N1 * CDIM];
__device__ bf16 g_fmh[N1 * 2 * CDIM], g_fml[N1 * 2 * CDIM];
__device__ bf16 g_s0h[N0 * CDIM], g_s0l[N0 * CDIM];

// =====================================================================
// split helpers
// =====================================================================
__device__ __forceinline__ void split1(float x, bf16& h, bf16& l)
{
    h = __float2bfloat16(x);
    l = __float2bfloat16(x - __bfloat162float(h));
}

__global__ void split_kernel(const float* __restrict__ src,
                             bf16* __restrict__ h, bf16* __restrict__ l, long long n4)
{
    for (long long i = blockIdx.x * (long long)blockDim.x + threadIdx.x;
         i < n4; i += (long long)gridDim.x * blockDim.x) {
        float4 v = reinterpret_cast<const float4*>(src)[i];
        union { bf16 b[4]; uint2 u; } uh, ul;
        split1(v.x, uh.b[0], ul.b[0]);
        split1(v.y, uh.b[1], ul.b[1]);
        split1(v.z, uh.b[2], ul.b[2]);
        split1(v.w, uh.b[3], ul.b[3]);
        reinterpret_cast<uint2*>(h)[i] = uh.u;
        reinterpret_cast<uint2*>(l)[i] = ul.u;
    }
}

// =====================================================================
// Tensor-core GEMM (mma.sync bf16, 3-pass split), TRANSB only:
//   Y = op( A[M,K] * B[N,K]^T )
// Block 128x128x32, 256 thr, 8 warps (4m x 2n), warp tile 32x64.
// cp.async 2-stage double-buffered smem (80 KB dynamic).
// MODE: 0 +bias | 1 (+bias)*rowmask | 2 *alpha | 3 relu(+bias)
//       4 (res + v + bias)*rowmask
// SPLIT_OUT: write (Yh, Yl) bf16 instead of fp32 Y.
// =====================================================================
__device__ __forceinline__ void mma16816(float* c, const unsigned* a, const unsigned* b)
{
    asm volatile(
        "mma.sync.aligned.m16n8k16.row.col.f32.bf16.bf16.f32 "
        "{%0,%1,%2,%3}, {%4,%5,%6,%7}, {%8,%9}, {%0,%1,%2,%3};\n"
        : "+f"(c[0]), "+f"(c[1]), "+f"(c[2]), "+f"(c[3])
        : "r"(a[0]), "r"(a[1]), "r"(a[2]), "r"(a[3]), "r"(b[0]), "r"(b[1]));
}

__device__ __forceinline__ void cp16(unsigned s, const void* g, bool v)
{
    asm volatile("cp.async.cg.shared.global [%0], [%1], 16, %2;\n"
                 :: "r"(s), "l"(g), "r"(v ? 16 : 0));
}
__device__ __forceinline__ void cp_commit()
{
    asm volatile("cp.async.commit_group;\n" ::);
}

#define GEMM_SMEM_BYTES 81920

template <int MODE, bool SPLIT_OUT>
__global__ void __launch_bounds__(256) mma_gemm_kernel(
    const bf16* __restrict__ Ahg, const bf16* __restrict__ Alg,
    const bf16* __restrict__ Bhg, const bf16* __restrict__ Blg,
    const float* __restrict__ bias, const float* __restrict__ res,
    const float* __restrict__ rowmask,
    float* __restrict__ Yg, bf16* __restrict__ Yhg, bf16* __restrict__ Ylg,
    int M, int N, int K, int ldx, int ldw, int ldy,
    long long sX, long long sW, long long sY, float alpha)
{
    constexpr int BM = 128, BN = 128, BK = 32;
    constexpr int LDA = 40;
    constexpr int SZ  = BM * LDA;          // elems per stage per tensor

    extern __shared__ __align__(16) char smem_raw[];
    bf16* sA_h = reinterpret_cast<bf16*>(smem_raw);       // [2][SZ]
    bf16* sA_l = sA_h + 2 * SZ;
    bf16* sB_h = sA_l + 2 * SZ;
    bf16* sB_l = sB_h + 2 * SZ;
    const unsigned sbase = (unsigned)__cvta_generic_to_shared(smem_raw);
    const unsigned offAh = 0;
    const unsigned offAl = 2 * SZ * 2;
    const unsigned offBh = 4 * SZ * 2;
    const unsigned offBl = 6 * SZ * 2;

    const bf16* Ah = Ahg + (long long)blockIdx.z * sX;
    const bf16* Al = Alg + (long long)blockIdx.z * sX;
    const bf16* Bh = Bhg + (long long)blockIdx.z * sW;
    const bf16* Bl = Blg + (long long)blockIdx.z * sW;
    float* Y  = Yg  ? Yg  + (long long)blockIdx.z * sY : nullptr;
    bf16*  Yh = Yhg ? Yhg + (long long)blockIdx.z * sY : nullptr;
    bf16*  Yl = Ylg ? Ylg + (long long)blockIdx.z * sY : nullptr;

    const int tid  = threadIdx.x;
    const int warp = tid >> 5;
    const int lane = tid & 31;
    const int wm   = warp & 3;          // 4 m-tiles of 32
    const int wn   = warp >> 2;         // 2 n-tiles of 64
    const int m0   = blockIdx.x * BM;
    const int n0   = blockIdx.y * BN;
    const int r    = lane >> 2;
    const int c2   = (lane & 3) * 2;

    const int lrow = tid >> 2;          // 0..63 (+64 on second pass)
    const int lq   = (tid & 3) * 8;     // 0,8,16,24

    float acc[2][8][4];
#pragma unroll
    for (int mt = 0; mt < 2; mt++)
#pragma unroll
        for (int nt = 0; nt < 8; nt++)
#pragma unroll
            for (int e = 0; e < 4; e++) acc[mt][nt][e] = 0.f;

    const int nk = K / BK;

    // ---- stage loader ----
    auto cp_stage = [&](int buf, int kt) {
        const int k0 = kt * BK;
#pragma unroll
        for (int it = 0; it < 2; it++) {
            const int row = lrow + it * 64;
            const unsigned soff = (unsigned)((buf * SZ + row * LDA + lq) * 2);
            const bool va = (m0 + row) < M;
            const long long ga = (long long)(m0 + row) * ldx + k0 + lq;
            cp16(sbase + offAh + soff, va ? (const void*)(Ah + ga) : (const void*)Ah, va);
            cp16(sbase + offAl + soff, va ? (const void*)(Al + ga) : (const void*)Al, va);
            const bool vb = (n0 + row) < N;
            const long long gb = (long long)(n0 + row) * ldw + k0 + lq;
            cp16(sbase + offBh + soff, vb ? (const void*)(Bh + gb) : (const void*)Bh, vb);
            cp16(sbase + offBl + soff, vb ? (const void*)(Bl + gb) : (const void*)Bl, vb);
        }
        cp_commit();
    };

    cp_stage(0, 0);

    for (int t = 0; t < nk; t++) {
        const int buf = t & 1;
        if (t + 1 < nk) {
            cp_stage(buf ^ 1, t + 1);
            asm volatile("cp.async.wait_group 1;\n" ::);
        } else {
            asm volatile("cp.async.wait_group 0;\n" ::);
        }
        __syncthreads();

        const bf16* cAh = sA_h + buf * SZ;
        const bf16* cAl = sA_l + buf * SZ;
        const bf16* cBh = sB_h + buf * SZ;
        const bf16* cBl = sB_l + buf * SZ;

#pragma unroll
        for (int ks = 0; ks < 2; ks++) {
            const int koff = ks * 16;
            unsigned ah[2][4], al[2][4], bh[8][2], bl[8][2];
#pragma unroll
            for (int mt = 0; mt < 2; mt++) {
                const int rb = (wm * 32 + mt * 16 + r) * LDA + koff + c2;
                ah[mt][0] = *reinterpret_cast<const unsigned*>(&cAh[rb]);
                ah[mt][1] = *reinterpret_cast<const unsigned*>(&cAh[rb + 8 * LDA]);
                ah[mt][2] = *reinterpret_cast<const unsigned*>(&cAh[rb + 8]);
                ah[mt][3] = *reinterpret_cast<const unsigned*>(&cAh[rb + 8 * LDA + 8]);
                al[mt][0] = *reinterpret_cast<const unsigned*>(&cAl[rb]);
                al[mt][1] = *reinterpret_cast<const unsigned*>(&cAl[rb + 8 * LDA]);
                al[mt][2] = *reinterpret_cast<const unsigned*>(&cAl[rb + 8]);
                al[mt][3] = *reinterpret_cast<const unsigned*>(&cAl[rb + 8 * LDA + 8]);
            }
#pragma unroll
            for (int nt = 0; nt < 8; nt++) {
                const int cb = (wn * 64 + nt * 8 + r) * LDA + koff + c2;
                bh[nt][0] = *reinterpret_cast<const unsigned*>(&cBh[cb]);
                bh[nt][1] = *reinterpret_cast<const unsigned*>(&cBh[cb + 8]);
                bl[nt][0] = *reinterpret_cast<const unsigned*>(&cBl[cb]);
                bl[nt][1] = *reinterpret_cast<const unsigned*>(&cBl[cb + 8]);
            }
#pragma unroll
            for (int mt = 0; mt < 2; mt++)
#pragma unroll
                for (int nt = 0; nt < 8; nt++) {
                    mma16816(acc[mt][nt], ah[mt], bh[nt]);
                    mma16816(acc[mt][nt], ah[mt], bl[nt]);
                    mma16816(acc[mt][nt], al[mt], bh[nt]);
                }
        }
        __syncthreads();
    }

    // ---- epilogue ----
#pragma unroll
    for (int mt = 0; mt < 2; mt++) {
#pragma unroll
        for (int nt = 0; nt < 8; nt++) {
#pragma unroll
            for (int e = 0; e < 4; e++) {
                const int gr = m0 + wm * 32 + mt * 16 + r + (e >= 2 ? 8 : 0);
                const int gc = n0 + wn * 64 + nt * 8 + c2 + (e & 1);
                if (gr >= M || gc >= N) continue;
                float v = acc[mt][nt][e];
                if (MODE == 0)      v = v + bias[gc];
                else if (MODE == 1) v = (v + bias[gc]) * rowmask[gr];
                else if (MODE == 2) v = v * alpha;
                else if (MODE == 3) v = fmaxf(v + bias[gc], 0.f);
                else if (MODE == 4) v = (res[(long long)gr * ldy + gc] + v + bias[gc]) * rowmask[gr];
                const long long off = (long long)gr * ldy + gc;
                if (SPLIT_OUT) {
                    bf16 h, l; split1(v, h, l);
                    Yh[off] = h; Yl[off] = l;
                } else {
                    Y[off] = v;
                }
            }
        }
    }
}

// =====================================================================
// V transpose: qkv[tok][2C + h*DH + d] -> Vt[h][d][tok]  (split bf16)
// =====================================================================
__global__ void __launch_bounds__(256) transpose_v_kernel(
    const bf16* __restrict__ qh, const bf16* __restrict__ ql,
    bf16* __restrict__ vh, bf16* __restrict__ vl, int n)
{
    __shared__ bf16 th[32][34], tl[32][34];
    const int hh = blockIdx.z;
    const int tok0 = blockIdx.x * 32, d0 = blockIdx.y * 32;
    const int tx = threadIdx.x, ty = threadIdx.y;
#pragma unroll
    for (int rr = ty; rr < 32; rr += 8) {
        const long long src = (long long)(tok0 + rr) * (3 * CDIM) + 2 * CDIM + hh * DHEAD + d0 + tx;
        th[rr][tx] = qh[src];
        tl[rr][tx] = ql[src];
    }
    __syncthreads();
#pragma unroll
    for (int rr = ty; rr < 32; rr += 8) {
        const long long dst = ((long long)hh * DHEAD + d0 + rr) * n + tok0 + tx;
        vh[dst] = th[tx][rr];
        vl[dst] = tl[tx][rr];
    }
}

// =====================================================================
// Masked-mean aggregation + concat -> split-bf16 cc
// =====================================================================
__global__ void __launch_bounds__(128) agg_concat_kernel(
    bf16* __restrict__ outh, bf16* __restrict__ outl,
    const float* __restrict__ sf, const float* __restrict__ child,
    const int* __restrict__ nbm)
{
    const int i = blockIdx.x;
    const int tid = threadIdx.x;
    __shared__ float mk[FANOUT];
    __shared__ float invd;
    if (tid < FANOUT) mk[tid] = (float)nbm[i * FANOUT + tid];
    __syncthreads();
    if (tid == 0) {
        float s = 0.f;
#pragma unroll
        for (int f = 0; f < FANOUT; f++) s += mk[f];
        invd = 1.f / fmaxf(s, 1.f);
    }
    __syncthreads();
    const float dinv = invd;
    const long long ob = (long long)i * (2 * CDIM) + tid * 4;

    float4 v0 = *reinterpret_cast<const float4*>(sf + (long long)i * CDIM + tid * 4);
    union { bf16 b[4]; uint2 u; } uh, ul;
    split1(v0.x, uh.b[0], ul.b[0]); split1(v0.y, uh.b[1], ul.b[1]);
    split1(v0.z, uh.b[2], ul.b[2]); split1(v0.w, uh.b[3], ul.b[3]);
    *reinterpret_cast<uint2*>(outh + ob) = uh.u;
    *reinterpret_cast<uint2*>(outl + ob) = ul.u;

    float4 acc = make_float4(0.f, 0.f, 0.f, 0.f);
    const float* cb = child + (long long)i * FANOUT * CDIM + tid * 4;
#pragma unroll
    for (int f = 0; f < FANOUT; f++) {
        float4 v = *reinterpret_cast<const float4*>(cb + f * CDIM);
        float w = mk[f];
        acc.x += v.x * w; acc.y += v.y * w; acc.z += v.z * w; acc.w += v.w * w;
    }
    acc.x *= dinv; acc.y *= dinv; acc.z *= dinv; acc.w *= dinv;
    split1(acc.x, uh.b[0], ul.b[0]); split1(acc.y, uh.b[1], ul.b[1]);
    split1(acc.z, uh.b[2], ul.b[2]); split1(acc.w, uh.b[3], ul.b[3]);
    *reinterpret_cast<uint2*>(outh + ob + CDIM) = uh.u;
    *reinterpret_cast<uint2*>(outl + ob + CDIM) = ul.u;
}

// =====================================================================
// Residual + LayerNorm: fp32 out + fused split-bf16 out
// =====================================================================
__global__ void __launch_bounds__(128) ln_res_kernel(
    float* __restrict__ out, bf16* __restrict__ outh, bf16* __restrict__ outl,
    const float* __restrict__ a, const float* __restrict__ b,
    const float* __restrict__ g, const float* __restrict__ be)
{
    const long long base = (long long)blockIdx.x * CDIM;
    const int tid = threadIdx.x;
    float4 va = *reinterpret_cast<const float4*>(a + base + tid * 4);
    float4 vb = *reinterpret_cast<const float4*>(b + base + tid * 4);
    float x0 = va.x + vb.x, x1 = va.y + vb.y, x2 = va.z + vb.z, x3 = va.w + vb.w;
    float s = x0 + x1 + x2 + x3;
    float q = x0 * x0 + x1 * x1 + x2 * x2 + x3 * x3;
#pragma unroll
    for (int o = 16; o; o >>= 1) {
        s += __shfl_xor_sync(0xffffffffu, s, o);
        q += __shfl_xor_sync(0xffffffffu, q, o);
    }
    __shared__ float shs[4], shq[4];
    if ((tid & 31) == 0) { shs[tid >> 5] = s; shq[tid >> 5] = q; }
    __syncthreads();
    s = shs[0] + shs[1] + shs[2] + shs[3];
    q = shq[0] + shq[1] + shq[2] + shq[3];
    const float mu  = s * (1.f / CDIM);
    const float var = q * (1.f / CDIM) - mu * mu;
    const float rr  = rsqrtf(var + 1e-5f);
    float4 vg  = *reinterpret_cast<const float4*>(g + tid * 4);
    float4 vbe = *reinterpret_cast<const float4*>(be + tid * 4);
    float4 o4;
    o4.x = (x0 - mu) * rr * vg.x + vbe.x;
    o4.y = (x1 - mu) * rr * vg.y + vbe.y;
    o4.z = (x2 - mu) * rr * vg.z + vbe.z;
    o4.w = (x3 - mu) * rr * vg.w + vbe.w;
    *reinterpret_cast<float4*>(out + base + tid * 4) = o4;
    union { bf16 bb[4]; uint2 u; } uh, ul;
    split1(o4.x, uh.bb[0], ul.bb[0]); split1(o4.y, uh.bb[1], ul.bb[1]);
    split1(o4.z, uh.bb[2], ul.bb[2]); split1(o4.w, uh.bb[3], ul.bb[3]);
    *reinterpret_cast<uint2*>(outh + base + tid * 4) = uh.u;
    *reinterpret_cast<uint2*>(outl + base + tid * 4) = ul.u;
}

// =====================================================================
// Row softmax; writes split-bf16 probabilities directly.
// =====================================================================
template <int CNT>
__global__ void __launch_bounds__(256) softmax_kernel(
    const float* __restrict__ S, bf16* __restrict__ Sh, bf16* __restrict__ Sl, int n)
{
    const long long rb = ((long long)blockIdx.y * n + blockIdx.x) * n;
    const float* row = S + rb;
    const int tid = threadIdx.x;
    float vals[CNT];
#pragma unroll
    for (int t = 0; t < CNT; t++) vals[t] = row[tid + t * 256];
    float m = -1e30f;
#pragma unroll
    for (int t = 0; t < CNT; t++) m = fmaxf(m, vals[t]);
    __shared__ float sh[8];
#pragma unroll
    for (int o = 16; o; o >>= 1) m = fmaxf(m, __shfl_xor_sync(0xffffffffu, m, o));
    if ((tid & 31) == 0) sh[tid >> 5] = m;
    __syncthreads();
    float mm = sh[0];
#pragma unroll
    for (int w = 1; w < 8; w++) mm = fmaxf(mm, sh[w]);
    float s = 0.f;
#pragma unroll
    for (int t = 0; t < CNT; t++) { vals[t] = expf(vals[t] - mm); s += vals[t]; }
    __syncthreads();
#pragma unroll
    for (int o = 16; o; o >>= 1) s += __shfl_xor_sync(0xffffffffu, s, o);
    if ((tid & 31) == 0) sh[tid >> 5] = s;
    __syncthreads();
    float tot = 0.f;
#pragma unroll
    for (int w = 0; w < 8; w++) tot += sh[w];
    const float inv = 1.f / tot;
#pragma unroll
    for (int t = 0; t < CNT; t++) {
        float p = vals[t] * inv;
        bf16 h, l; split1(p, h, l);
        Sh[rb + tid + t * 256] = h;
        Sl[rb + tid + t * 256] = l;
    }
}

// =====================================================================
// Host-side helpers
// =====================================================================
template <int MODE, bool SO>
static inline void launch_mma(const bf16* Ah, const bf16* Al,
                              const bf16* Bh, const bf16* Bl,
                              const float* bias, const float* res, const float* rm,
                              float* Y, bf16* Yh, bf16* Yl,
                              int M, int N, int K, int ldx, int ldw, int ldy,
                              long long sX = 0, long long sW = 0, long long sY = 0,
                              int batch = 1, float alpha = 1.f)
{
    dim3 grid((M + 127) / 128, (N + 127) / 128, batch);
    mma_gemm_kernel<MODE, SO><<<grid, 256, GEMM_SMEM_BYTES>>>(
        Ah, Al, Bh, Bl, bias, res, rm, Y, Yh, Yl,
        M, N, K, ldx, ldw, ldy, sX, sW, sY, alpha);
}

static inline void launch_split(const float* s, bf16* h, bf16* l, long long cnt)
{
    long long n4 = cnt / 4;
    int grid = (int)((n4 + 255) / 256);
    if (grid > 4096) grid = 4096;
    split_kernel<<<grid, 256>>>(s, h, l, n4);
}

// Cached scratch pointers
static float *s0a, *s0b, *s1a, *s1b, *s2, *hl, *h1, *h2p, *scp;
static bf16 *f2h, *f2l, *f1h, *f1l, *f0h, *f0l;
static bf16 *wembh, *wembl, *wsageh, *wsagel, *wqkvh, *wqkvl, *wouth, *woutl;
static bf16 *wf1h, *wf1l, *wf2h, *wf2l, *wclsh, *wclsl;
static bf16 *cch, *ccl, *h1h, *h1l, *h2h, *h2l, *qkvh, *qkvl;
static bf16 *sch, *scl, *vth, *vtl, *aoh, *aol, *fmh, *fml, *s0h, *s0l;
static bool g_ptrs_ready = false;

#define SYM(p, s) cudaGetSymbolAddress((void**)&(p), s)
#define SETSMEM(MODE, SO) \
    cudaFuncSetAttribute(mma_gemm_kernel<MODE, SO>, \
        cudaFuncAttributeMaxDynamicSharedMemorySize, GEMM_SMEM_BYTES)

static void resolve_ptrs()
{
    if (g_ptrs_ready) return;
    SYM(s0a, g_s0a); SYM(s0b, g_s0b); SYM(s1a, g_s1a); SYM(s1b, g_s1b);
    SYM(s2, g_s2); SYM(hl, g_hlocal); SYM(h1, g_h1); SYM(h2p, g_h2); SYM(scp, g_scores);
    SYM(f2h, g_f2h); SYM(f2l, g_f2l); SYM(f1h, g_f1h); SYM(f1l, g_f1l);
    SYM(f0h, g_f0h); SYM(f0l, g_f0l);
    SYM(wembh, g_wembh); SYM(wembl, g_wembl);
    SYM(wsageh, g_wsageh); SYM(wsagel, g_wsagel);
    SYM(wqkvh, g_wqkvh); SYM(wqkvl, g_wqkvl);
    SYM(wouth, g_wouth); SYM(woutl, g_woutl);
    SYM(wf1h, g_wf1h); SYM(wf1l, g_wf1l);
    SYM(wf2h, g_wf2h); SYM(wf2l, g_wf2l);
    SYM(wclsh, g_wclsh); SYM(wclsl, g_wclsl);
    SYM(cch, g_cch); SYM(ccl, g_ccl);
    SYM(h1h, g_h1h); SYM(h1l, g_h1l);
    SYM(h2h, g_h2h); SYM(h2l, g_h2l);
    SYM(qkvh, g_qkvh); SYM(qkvl, g_qkvl);
    SYM(sch, g_sch); SYM(scl, g_scl);
    SYM(vth, g_vth); SYM(vtl, g_vtl);
    SYM(aoh, g_aoh); SYM(aol, g_aol);
    SYM(fmh, g_fmh); SYM(fml, g_fml);
    SYM(s0h, g_s0h); SYM(s0l, g_s0l);
    SETSMEM(0, false); SETSMEM(0, true);
    SETSMEM(1, false);
    SETSMEM(2, false); SETSMEM(2, true);
    SETSMEM(3, true);
    SETSMEM(4, false); SETSMEM(4, true);
    g_ptrs_ready = true;
}

extern "C" void kernel_launch(void* const* d_in, const int* in_sizes, int n_in,
                              void* d_out, int out_size)
{
    (void)in_sizes; (void)n_in; (void)out_size;
    const float* feats0  = (const float*)d_in[0];
    const float* feats1  = (const float*)d_in[1];
    const float* feats2  = (const float*)d_in[2];
    const float* nmask0  = (const float*)d_in[3];
    const float* nmask1  = (const float*)d_in[4];
    const float* nmask2  = (const float*)d_in[5];
    const int*   nbmask0 = (const int*)d_in[6];
    const int*   nbmask1 = (const int*)d_in[7];
    const float* emb_w   = (const float*)d_in[8];
    const float* emb_b   = (const float*)d_in[9];
    const float* sage_w  = (const float*)d_in[10];
    const float* sage_b  = (const float*)d_in[11];
    const float* qkv_w   = (const float*)d_in[12];
    const float* qkv_b   = (const float*)d_in[13];
    const float* out_w   = (const float*)d_in[14];
    const float* out_b   = (const float*)d_in[15];
    const float* n1_g    = (const float*)d_in[16];
    const float* n1_b    = (const float*)d_in[17];
    const float* n2_g    = (const float*)d_in[18];
    const float* n2_b    = (const float*)d_in[19];
    const float* ffn_w1  = (const float*)d_in[20];
    const float* ffn_b1  = (const float*)d_in[21];
    const float* ffn_w2  = (const float*)d_in[22];
    const float* ffn_b2  = (const float*)d_in[23];
    const float* cls_w   = (const float*)d_in[24];
    const float* cls_b   = (const float*)d_in[25];
    float* out = (float*)d_out;

    resolve_ptrs();

    // ---- pre-split inputs & weights (bf16 hi/lo) ----
    launch_split(feats2, f2h, f2l, (long long)N2 * INDIM);
    launch_split(feats1, f1h, f1l, (long long)N1 * INDIM);
    launch_split(feats0, f0h, f0l, (long long)N0 * INDIM);
    launch_split(emb_w,  wembh, wembl, (long long)CDIM * INDIM);
    launch_split(sage_w, wsageh, wsagel, (long long)NL * CDIM * 2 * CDIM);
    launch_split(qkv_w,  wqkvh, wqkvl, (long long)NL * 3 * CDIM * CDIM);
    launch_split(out_w,  wouth, woutl, (long long)NL * CDIM * CDIM);
    launch_split(ffn_w1, wf1h, wf1l, (long long)NL * 2 * CDIM * CDIM);
    launch_split(ffn_w2, wf2h, wf2l, (long long)NL * CDIM * 2 * CDIM);
    launch_split(cls_w,  wclsh, wclsl, (long long)NCLS * CDIM);

    // ---- embeddings ----
    launch_mma<1, false>(f2h, f2l, wembh, wembl, emb_b, nullptr, nmask2,
                         s2, nullptr, nullptr, N2, CDIM, INDIM, INDIM, INDIM, CDIM);
    launch_mma<1, false>(f1h, f1l, wembh, wembl, emb_b, nullptr, nmask1,
                         s1a, nullptr, nullptr, N1, CDIM, INDIM, INDIM, INDIM, CDIM);
    launch_mma<1, false>(f0h, f0l, wembh, wembl, emb_b, nullptr, nmask0,
                         s0a, nullptr, nullptr, N0, CDIM, INDIM, INDIM, INDIM, CDIM);

    struct Step { int li, n; float *sf, *child, *outb; const int* nbm; const float* nm; bool last; };
    Step steps[3] = {
        {0, N1, s1a, s2,  s1b, nbmask1, nmask1, false},
        {0, N0, s0a, s1a, s0b, nbmask0, nmask0, false},
        {1, N0, s0b, s1b, nullptr, nbmask0, nmask0, true},
    };

    const float scale = 1.f / sqrtf((float)DHEAD);

    for (int si = 0; si < 3; si++) {
        const Step& st = steps[si];
        const int li = st.li, n = st.n;
        const bf16* swh = wsageh + (long long)li * CDIM * 2 * CDIM;
        const bf16* swl = wsagel + (long long)li * CDIM * 2 * CDIM;
        const float* sb = sage_b + li * CDIM;
        const bf16* qwh = wqkvh + (long long)li * 3 * CDIM * CDIM;
        const bf16* qwl = wqkvl + (long long)li * 3 * CDIM * CDIM;
        const float* qb = qkv_b + li * 3 * CDIM;
        const bf16* owh = wouth + (long long)li * CDIM * CDIM;
        const bf16* owl = woutl + (long long)li * CDIM * CDIM;
        const float* ob = out_b + li * CDIM;
        const float* g1 = n1_g + li * CDIM, *b1 = n1_b + li * CDIM;
        const float* g2 = n2_g + li * CDIM, *b2 = n2_b + li * CDIM;
        const bf16* f1wh = wf1h + (long long)li * 2 * CDIM * CDIM;
        const bf16* f1wl = wf1l + (long long)li * 2 * CDIM * CDIM;
        const float* fb1 = ffn_b1 + li * 2 * CDIM;
        const bf16* f2wh = wf2h + (long long)li * CDIM * 2 * CDIM;
        const bf16* f2wl = wf2l + (long long)li * CDIM * 2 * CDIM;
        const float* fb2 = ffn_b2 + li * CDIM;

        // 1) aggregate + concat -> split cc
        agg_concat_kernel<<<n, 128>>>(cch, ccl, st.sf, st.child, st.nbm);
        // 2) h_local = cc @ sage_w^T + sage_b
        launch_mma<0, false>(cch, ccl, swh, swl, sb, nullptr, nullptr,
                             hl, nullptr, nullptr,
                             n, CDIM, 2 * CDIM, 2 * CDIM, 2 * CDIM, CDIM);
        // 3) h1 = LN(sf + h_local)
        ln_res_kernel<<<n, 128>>>(h1, h1h, h1l, st.sf, hl, g1, b1);
        // 4) qkv
        launch_mma<0, true>(h1h, h1l, qwh, qwl, qb, nullptr, nullptr,
                            nullptr, qkvh, qkvl,
                            n, 3 * CDIM, CDIM, CDIM, CDIM, 3 * CDIM);
        // 5) scores = scale * Q K^T  (batched heads)
        launch_mma<2, false>(qkvh, qkvl, qkvh + CDIM, qkvl + CDIM,
                             nullptr, nullptr, nullptr,
                             scp, nullptr, nullptr,
                             n, n, DHEAD, 3 * CDIM, 3 * CDIM, n,
                             DHEAD, DHEAD, (long long)n * n, NHEAD, scale);
        // 6) softmax -> split probabilities
        if (n == N1) softmax_kernel<16><<<dim3(N1, NHEAD), 256>>>(scp, sch, scl, n);
        else         softmax_kernel<1><<<dim3(N0, NHEAD), 256>>>(scp, sch, scl, n);
        // 6b) transpose V -> Vt[h][d][tok]
        transpose_v_kernel<<<dim3(n / 32, DHEAD / 32, NHEAD), dim3(32, 8)>>>(
            qkvh, qkvl, vth, vtl, n);
        // 7) O_h = P_h @ V_h^T (now TRANSB on Vt)
        launch_mma<2, true>(sch, scl, vth, vtl,
                            nullptr, nullptr, nullptr,
                            nullptr, aoh, aol,
                            n, DHEAD, n, n, n, CDIM,
                            (long long)n * n, (long long)DHEAD * n, DHEAD, NHEAD, 1.f);
        // 8) proj
        launch_mma<0, false>(aoh, aol, owh, owl, ob, nullptr, nullptr,
                             hl, nullptr, nullptr,
                             n, CDIM, CDIM, CDIM, CDIM, CDIM);
        // 9) h2 = LN(h1 + proj)
        ln_res_kernel<<<n, 128>>>(h2p, h2h, h2l, h1, hl, g2, b2);
        // 10) mid = relu(...)
        launch_mma<3, true>(h2h, h2l, f1wh, f1wl, fb1, nullptr, nullptr,
                            nullptr, fmh, fml,
                            n, 2 * CDIM, CDIM, CDIM, CDIM, 2 * CDIM);
        // 11) state
        if (st.last)
            launch_mma<4, true>(fmh, fml, f2wh, f2wl, fb2, h2p, st.nm,
                                nullptr, s0h, s0l,
                                n, CDIM, 2 * CDIM, 2 * CDIM, 2 * CDIM, CDIM);
        else
            launch_mma<4, false>(fmh, fml, f2wh, f2wl, fb2, h2p, st.nm,
                                 st.outb, nullptr, nullptr,
                                 n, CDIM, 2 * CDIM, 2 * CDIM, 2 * CDIM, CDIM);
    }

    // ---- classifier ----
    launch_mma<0, false>(s0h, s0l, wclsh, wclsl, cls_b, nullptr, nullptr,
                         out, nullptr, nullptr,
                         N0, NCLS, CDIM, CDIM, CDIM, NCLS);
}